// round 3
// baseline (speedup 1.0000x reference)
#include <cuda_runtime.h>

// Problem constants
#define BB   2
#define TT   2048
#define DD   1024
#define HH   8
#define DKK  128
#define MM   (BB*TT)   // 4096 rows for the projections

// ---------------------------------------------------------------------------
// Scratch (device globals — no allocations allowed)
// ---------------------------------------------------------------------------
__device__ float g_Q[(size_t)BB*HH*TT*DKK];        // [B,H,T,DK] 16 MB
__device__ float g_K[(size_t)BB*HH*TT*DKK];        // 16 MB
__device__ float g_V[(size_t)BB*HH*TT*DKK];        // 16 MB
__device__ float g_AO[(size_t)BB*TT*DD];           // [B,T,D] attention output, 16 MB
__device__ float g_biasT[(size_t)BB*HH*TT*TT];     // [B,H,Tq,Tk] transposed bias, 256 MB

// ---------------------------------------------------------------------------
// Kernel 1: fused Q/K/V projection.  out[m,n] = sum_k X[m,k] * W[n,k]
// 64x64 tile, 16-deep k, 256 threads, 4x4 accum per thread.
// Output written directly in [B,H,T,DK] layout.
// ---------------------------------------------------------------------------
__global__ void __launch_bounds__(256) gemm_qkv_kernel(
    const float* __restrict__ q_in, const float* __restrict__ k_in,
    const float* __restrict__ v_in, const float* __restrict__ Wq,
    const float* __restrict__ Wk,   const float* __restrict__ Wv)
{
    const int z = blockIdx.z;
    const float* X = (z == 0) ? q_in : (z == 1) ? k_in : v_in;
    const float* W = (z == 0) ? Wq   : (z == 1) ? Wk   : Wv;
    float* outp    = (z == 0) ? g_Q  : (z == 1) ? g_K  : g_V;

    __shared__ float As[16][64];  // [k][m]
    __shared__ float Bs[16][64];  // [k][n]

    const int m0 = blockIdx.x * 64;
    const int n0 = blockIdx.y * 64;
    const int tx = threadIdx.x, ty = threadIdx.y;
    const int tid = ty * 16 + tx;
    const int lr = tid >> 2;          // 0..63 (row within tile)
    const int lc = (tid & 3) << 2;    // 0,4,8,12 (k offset)

    float acc[4][4] = {};

    const float* Xp = X + (size_t)(m0 + lr) * DD + lc;
    const float* Wp = W + (size_t)(n0 + lr) * DD + lc;

    for (int k0 = 0; k0 < DD; k0 += 16) {
        float4 a = *(const float4*)(Xp + k0);
        float4 w = *(const float4*)(Wp + k0);
        __syncthreads();
        As[lc + 0][lr] = a.x; As[lc + 1][lr] = a.y; As[lc + 2][lr] = a.z; As[lc + 3][lr] = a.w;
        Bs[lc + 0][lr] = w.x; Bs[lc + 1][lr] = w.y; Bs[lc + 2][lr] = w.z; Bs[lc + 3][lr] = w.w;
        __syncthreads();
#pragma unroll
        for (int kk = 0; kk < 16; kk++) {
            float4 av = *(const float4*)&As[kk][ty * 4];
            float4 bv = *(const float4*)&Bs[kk][tx * 4];
            acc[0][0] += av.x * bv.x; acc[0][1] += av.x * bv.y; acc[0][2] += av.x * bv.z; acc[0][3] += av.x * bv.w;
            acc[1][0] += av.y * bv.x; acc[1][1] += av.y * bv.y; acc[1][2] += av.y * bv.z; acc[1][3] += av.y * bv.w;
            acc[2][0] += av.z * bv.x; acc[2][1] += av.z * bv.y; acc[2][2] += av.z * bv.z; acc[2][3] += av.z * bv.w;
            acc[3][0] += av.w * bv.x; acc[3][1] += av.w * bv.y; acc[3][2] += av.w * bv.z; acc[3][3] += av.w * bv.w;
        }
    }

    // Scatter into [B,H,T,DK]: m = b*T+t ; n = h*DK+dk
#pragma unroll
    for (int i = 0; i < 4; i++) {
        int m = m0 + ty * 4 + i;
        int b = m >> 11;        // /2048
        int t = m & 2047;
#pragma unroll
        for (int j = 0; j < 4; j++) {
            int n  = n0 + tx * 4 + j;
            int h  = n >> 7;    // /128
            int dk = n & 127;
            outp[((size_t)(b * HH + h) * TT + t) * DKK + dk] = acc[i][j];
        }
    }
}

// ---------------------------------------------------------------------------
// Kernel 2: rel_bias transpose  [B,Tq,Tk,H] -> [B,H,Tq,Tk]
// One CTA per (b,q). Reads hit L1 after first head pass; writes coalesced.
// ---------------------------------------------------------------------------
__global__ void __launch_bounds__(256) bias_transpose_kernel(const float* __restrict__ rb)
{
    const int bq = blockIdx.x;            // 0..B*T-1
    const int b  = bq >> 11;
    const int q  = bq & 2047;
    const float* src = rb + (size_t)bq * TT * HH;
#pragma unroll
    for (int h = 0; h < HH; h++) {
        float* dst = g_biasT + ((size_t)(b * HH + h) * TT + q) * TT;
        for (int k = threadIdx.x; k < TT; k += 256)
            dst[k] = src[(size_t)k * HH + h];
    }
}

// ---------------------------------------------------------------------------
// Kernel 3: flash attention with additive bias + causal mask.
// CTA = (b, h, 64-row q tile). 256 threads (16x16), 4x4 score block per thread,
// O accumulator 4 rows x 8 dk columns per thread.
// ---------------------------------------------------------------------------
#define SSTR 132   // padded row stride for 128-wide tiles (bank-conflict relief)

__global__ void __launch_bounds__(256) attn_kernel(const int* __restrict__ is_causal_p)
{
    extern __shared__ float smem[];
    float* Qs = smem;                 // 64 x SSTR
    float* Ks = Qs + 64 * SSTR;       // 64 x SSTR
    float* Vs = Ks + 64 * SSTR;       // 64 x SSTR
    float* Ps = Vs + 64 * SSTR;       // 64 x 64

    // reverse q-tile order so the longest (most k-tiles) CTAs start first
    const int q0 = ((int)gridDim.x - 1 - (int)blockIdx.x) * 64;
    const int h  = blockIdx.y;
    const int b  = blockIdx.z;
    const int tx = threadIdx.x, ty = threadIdx.y;
    const int tid = ty * 16 + tx;
    const bool causal = (is_causal_p[0] != 0);

    const float* Qg = g_Q + (size_t)(b * HH + h) * TT * DKK;
    const float* Kg = g_K + (size_t)(b * HH + h) * TT * DKK;
    const float* Vg = g_V + (size_t)(b * HH + h) * TT * DKK;
    const float* Bg = g_biasT + (size_t)(b * HH + h) * TT * TT;

    const float qscale = 0.08838834764831845f;  // 1/sqrt(128)

    // Load Q tile (scaled)
    {
        const int r0 = tid >> 5;
        const int d4 = (tid & 31) << 2;
#pragma unroll
        for (int it = 0; it < 8; it++) {
            int row = r0 + it * 8;
            float4 v = *(const float4*)(Qg + (size_t)(q0 + row) * DKK + d4);
            v.x *= qscale; v.y *= qscale; v.z *= qscale; v.w *= qscale;
            *(float4*)(Qs + row * SSTR + d4) = v;
        }
    }

    float m_i[4], l_i[4], O[4][8];
#pragma unroll
    for (int i = 0; i < 4; i++) {
        m_i[i] = -1e30f; l_i[i] = 0.0f;
#pragma unroll
        for (int j = 0; j < 8; j++) O[i][j] = 0.0f;
    }

    const int ntiles = causal ? (q0 / 64 + 1) : (TT / 64);

    for (int kt = 0; kt < ntiles; kt++) {
        const int k0 = kt * 64;

        // Load K,V tiles
        {
            const int r0 = tid >> 5;
            const int d4 = (tid & 31) << 2;
#pragma unroll
            for (int it = 0; it < 8; it++) {
                int row = r0 + it * 8;
                *(float4*)(Ks + row * SSTR + d4) = *(const float4*)(Kg + (size_t)(k0 + row) * DKK + d4);
                *(float4*)(Vs + row * SSTR + d4) = *(const float4*)(Vg + (size_t)(k0 + row) * DKK + d4);
            }
        }
        __syncthreads();

        // S = (Q * scale) K^T
        float s[4][4] = {};
#pragma unroll 4
        for (int d0 = 0; d0 < DKK; d0 += 4) {
            float4 qv[4], kv[4];
#pragma unroll
            for (int i = 0; i < 4; i++) qv[i] = *(const float4*)(Qs + (ty * 4 + i) * SSTR + d0);
#pragma unroll
            for (int j = 0; j < 4; j++) kv[j] = *(const float4*)(Ks + (tx * 4 + j) * SSTR + d0);
#pragma unroll
            for (int i = 0; i < 4; i++)
#pragma unroll
                for (int j = 0; j < 4; j++)
                    s[i][j] += qv[i].x * kv[j].x + qv[i].y * kv[j].y +
                               qv[i].z * kv[j].z + qv[i].w * kv[j].w;
        }

        // Additive bias (coalesced from transposed layout)
#pragma unroll
        for (int i = 0; i < 4; i++) {
            int q = q0 + ty * 4 + i;
            float4 bb = *(const float4*)(Bg + (size_t)q * TT + k0 + tx * 4);
            s[i][0] += bb.x; s[i][1] += bb.y; s[i][2] += bb.z; s[i][3] += bb.w;
        }
        // Causal mask
        if (causal) {
#pragma unroll
            for (int i = 0; i < 4; i++) {
                int q = q0 + ty * 4 + i;
#pragma unroll
                for (int j = 0; j < 4; j++)
                    if (k0 + tx * 4 + j > q) s[i][j] = -1e30f;
            }
        }

        // Online softmax update (row = 16 lanes sharing ty; xor-shuffle over 1..8)
#pragma unroll
        for (int i = 0; i < 4; i++) {
            float rmax = fmaxf(fmaxf(s[i][0], s[i][1]), fmaxf(s[i][2], s[i][3]));
#pragma unroll
            for (int off = 8; off >= 1; off >>= 1)
                rmax = fmaxf(rmax, __shfl_xor_sync(0xffffffffu, rmax, off));
            float mnew = fmaxf(m_i[i], rmax);
            float corr = __expf(m_i[i] - mnew);
            float p0 = __expf(s[i][0] - mnew);
            float p1 = __expf(s[i][1] - mnew);
            float p2 = __expf(s[i][2] - mnew);
            float p3 = __expf(s[i][3] - mnew);
            float psum = p0 + p1 + p2 + p3;
#pragma unroll
            for (int off = 8; off >= 1; off >>= 1)
                psum += __shfl_xor_sync(0xffffffffu, psum, off);
            l_i[i] = l_i[i] * corr + psum;
            m_i[i] = mnew;
#pragma unroll
            for (int j = 0; j < 8; j++) O[i][j] *= corr;
            *(float4*)(Ps + (ty * 4 + i) * 64 + tx * 4) = make_float4(p0, p1, p2, p3);
        }
        __syncthreads();

        // O += P @ V   (thread owns 4 q-rows x 8 dk cols at d = tx*8)
#pragma unroll 2
        for (int kk = 0; kk < 64; kk++) {
            float4 va = *(const float4*)(Vs + kk * SSTR + tx * 8);
            float4 vb = *(const float4*)(Vs + kk * SSTR + tx * 8 + 4);
#pragma unroll
            for (int i = 0; i < 4; i++) {
                float p = Ps[(ty * 4 + i) * 64 + kk];
                O[i][0] += p * va.x; O[i][1] += p * va.y; O[i][2] += p * va.z; O[i][3] += p * va.w;
                O[i][4] += p * vb.x; O[i][5] += p * vb.y; O[i][6] += p * vb.z; O[i][7] += p * vb.w;
            }
        }
        __syncthreads();
    }

    // Epilogue: normalize and write [B,T,D] (= transpose(0,2,1,3).reshape)
#pragma unroll
    for (int i = 0; i < 4; i++) {
        int q = q0 + ty * 4 + i;
        float inv = 1.0f / l_i[i];
        float* dst = g_AO + (size_t)(b * TT + q) * DD + h * DKK + tx * 8;
        *(float4*)dst       = make_float4(O[i][0] * inv, O[i][1] * inv, O[i][2] * inv, O[i][3] * inv);
        *(float4*)(dst + 4) = make_float4(O[i][4] * inv, O[i][5] * inv, O[i][6] * inv, O[i][7] * inv);
    }
}

// ---------------------------------------------------------------------------
// Kernel 4: output projection  out = AO @ Wo^T + bo
// ---------------------------------------------------------------------------
__global__ void __launch_bounds__(256) gemm_out_kernel(
    const float* __restrict__ Wo, const float* __restrict__ bo,
    float* __restrict__ out)
{
    __shared__ float As[16][64];
    __shared__ float Bs[16][64];

    const int m0 = blockIdx.x * 64;
    const int n0 = blockIdx.y * 64;
    const int tx = threadIdx.x, ty = threadIdx.y;
    const int tid = ty * 16 + tx;
    const int lr = tid >> 2;
    const int lc = (tid & 3) << 2;

    float acc[4][4] = {};

    const float* Xp = g_AO + (size_t)(m0 + lr) * DD + lc;
    const float* Wp = Wo   + (size_t)(n0 + lr) * DD + lc;

    for (int k0 = 0; k0 < DD; k0 += 16) {
        float4 a = *(const float4*)(Xp + k0);
        float4 w = *(const float4*)(Wp + k0);
        __syncthreads();
        As[lc + 0][lr] = a.x; As[lc + 1][lr] = a.y; As[lc + 2][lr] = a.z; As[lc + 3][lr] = a.w;
        Bs[lc + 0][lr] = w.x; Bs[lc + 1][lr] = w.y; Bs[lc + 2][lr] = w.z; Bs[lc + 3][lr] = w.w;
        __syncthreads();
#pragma unroll
        for (int kk = 0; kk < 16; kk++) {
            float4 av = *(const float4*)&As[kk][ty * 4];
            float4 bv = *(const float4*)&Bs[kk][tx * 4];
            acc[0][0] += av.x * bv.x; acc[0][1] += av.x * bv.y; acc[0][2] += av.x * bv.z; acc[0][3] += av.x * bv.w;
            acc[1][0] += av.y * bv.x; acc[1][1] += av.y * bv.y; acc[1][2] += av.y * bv.z; acc[1][3] += av.y * bv.w;
            acc[2][0] += av.z * bv.x; acc[2][1] += av.z * bv.y; acc[2][2] += av.z * bv.z; acc[2][3] += av.z * bv.w;
            acc[3][0] += av.w * bv.x; acc[3][1] += av.w * bv.y; acc[3][2] += av.w * bv.z; acc[3][3] += av.w * bv.w;
        }
    }

    float4 bias = *(const float4*)(bo + n0 + tx * 4);
#pragma unroll
    for (int i = 0; i < 4; i++) {
        int m = m0 + ty * 4 + i;
        float4 r = make_float4(acc[i][0] + bias.x, acc[i][1] + bias.y,
                               acc[i][2] + bias.z, acc[i][3] + bias.w);
        *(float4*)(out + (size_t)m * DD + n0 + tx * 4) = r;
    }
}

// ---------------------------------------------------------------------------
// Launcher. Inputs (metadata order):
// 0 query, 1 key, 2 value, 3 mask(all-false, unused), 4 rel_bias,
// 5 Wq, 6 Wk, 7 Wv, 8 Wo, 9 bo, 10 is_causal
// ---------------------------------------------------------------------------
extern "C" void kernel_launch(void* const* d_in, const int* in_sizes, int n_in,
                              void* d_out, int out_size)
{
    (void)in_sizes; (void)n_in; (void)out_size;
    const float* query    = (const float*)d_in[0];
    const float* key      = (const float*)d_in[1];
    const float* value    = (const float*)d_in[2];
    const float* rel_bias = (const float*)d_in[4];
    const float* Wq       = (const float*)d_in[5];
    const float* Wk       = (const float*)d_in[6];
    const float* Wv       = (const float*)d_in[7];
    const float* Wo       = (const float*)d_in[8];
    const float* bo       = (const float*)d_in[9];
    const int* is_causal  = (const int*)d_in[10];
    float* out            = (float*)d_out;

    dim3 blk(16, 16);

    // 1) QKV projections (3 GEMMs fused in z)
    gemm_qkv_kernel<<<dim3(MM / 64, DD / 64, 3), blk>>>(query, key, value, Wq, Wk, Wv);

    // 2) Bias transpose (independent of QKV, serialized on default stream)
    bias_transpose_kernel<<<BB * TT, 256>>>(rel_bias);

    // 3) Flash attention with bias + causal
    const int attn_smem = (3 * 64 * SSTR + 64 * 64) * (int)sizeof(float);  // 117760 B
    cudaFuncSetAttribute(attn_kernel, cudaFuncAttributeMaxDynamicSharedMemorySize, attn_smem);
    attn_kernel<<<dim3(TT / 64, HH, BB), blk, attn_smem>>>(is_causal);

    // 4) Output projection + bias
    gemm_out_kernel<<<dim3(MM / 64, DD / 64), blk>>>(Wo, bo, out);
}

// round 4
// speedup vs baseline: 2.7372x; 2.7372x over previous
#include <cuda_runtime.h>

// Problem constants
#define BB   2
#define TT   2048
#define DD   1024
#define HH   8
#define DKK  128
#define MM   (BB*TT)

// ---------------------------------------------------------------------------
// Scratch (device globals — no allocations allowed)
// ---------------------------------------------------------------------------
__device__ float g_Q[(size_t)BB*HH*TT*DKK];
__device__ float g_K[(size_t)BB*HH*TT*DKK];
__device__ float g_V[(size_t)BB*HH*TT*DKK];
__device__ float g_AO[(size_t)BB*TT*DD];
__device__ float g_biasT[(size_t)BB*HH*TT*TT];   // [B,H,Tq,Tk] 256 MB

// ---------------------------------------------------------------------------
// TF32 mma helpers
// ---------------------------------------------------------------------------
__device__ __forceinline__ unsigned f2tf(float f) {
    unsigned u;
    asm("cvt.rna.tf32.f32 %0, %1;" : "=r"(u) : "f"(f));
    return u;
}

__device__ __forceinline__ void mma_tf32(float c[4],
    unsigned a0, unsigned a1, unsigned a2, unsigned a3,
    unsigned b0, unsigned b1)
{
    asm volatile(
        "mma.sync.aligned.m16n8k8.row.col.f32.tf32.tf32.f32 "
        "{%0,%1,%2,%3}, {%4,%5,%6,%7}, {%8,%9}, {%0,%1,%2,%3};"
        : "+f"(c[0]), "+f"(c[1]), "+f"(c[2]), "+f"(c[3])
        : "r"(a0), "r"(a1), "r"(a2), "r"(a3), "r"(b0), "r"(b1));
}

// ---------------------------------------------------------------------------
// TF32 GEMM core: out[m,n] = sum_k X[m,k] * W[n,k]
// 128x128 CTA tile, BK=32, 256 threads = 8 warps (2m x 4n), warp tile 64x32.
// smem stored [k][m(+pad)] stride 136 -> frag LDS banks (8c+g) conflict-free.
// ---------------------------------------------------------------------------
#define GSTR 136

struct GemmAcc { float c[4][4][4]; };

__device__ __forceinline__ void gemm_tf32_body(
    const float* __restrict__ X, const float* __restrict__ W,
    int m0, int n0, float* As, float* Bs, GemmAcc& A)
{
    const int tid = threadIdx.x;
    const int lane = tid & 31, wid = tid >> 5;
    const int wm = (wid & 1) * 64, wn = (wid >> 1) * 32;
    const int g = lane >> 2, c = lane & 3;

#pragma unroll
    for (int mf = 0; mf < 4; mf++)
#pragma unroll
        for (int nf = 0; nf < 4; nf++)
#pragma unroll
            for (int r = 0; r < 4; r++) A.c[mf][nf][r] = 0.0f;

    const int lm  = tid & 127;      // row handled by this thread in loader
    const int kq  = tid >> 7;       // 0/1

    for (int kt = 0; kt < DD; kt += 32) {
        __syncthreads();
#pragma unroll
        for (int j = 0; j < 4; j++) {
            int k4 = (kq + j * 2) * 4;            // 0..28
            float4 a = *(const float4*)(X + (size_t)(m0 + lm) * DD + kt + k4);
            float4 w = *(const float4*)(W + (size_t)(n0 + lm) * DD + kt + k4);
            As[(k4 + 0) * GSTR + lm] = a.x; As[(k4 + 1) * GSTR + lm] = a.y;
            As[(k4 + 2) * GSTR + lm] = a.z; As[(k4 + 3) * GSTR + lm] = a.w;
            Bs[(k4 + 0) * GSTR + lm] = w.x; Bs[(k4 + 1) * GSTR + lm] = w.y;
            Bs[(k4 + 2) * GSTR + lm] = w.z; Bs[(k4 + 3) * GSTR + lm] = w.w;
        }
        __syncthreads();

#pragma unroll
        for (int ks = 0; ks < 32; ks += 8) {
            unsigned af[4][4];
#pragma unroll
            for (int mf = 0; mf < 4; mf++) {
                int mbase = wm + mf * 16 + g;
                af[mf][0] = f2tf(As[(ks + c) * GSTR + mbase]);
                af[mf][1] = f2tf(As[(ks + c) * GSTR + mbase + 8]);
                af[mf][2] = f2tf(As[(ks + c + 4) * GSTR + mbase]);
                af[mf][3] = f2tf(As[(ks + c + 4) * GSTR + mbase + 8]);
            }
#pragma unroll
            for (int nf = 0; nf < 4; nf++) {
                int nbase = wn + nf * 8 + g;
                unsigned b0 = f2tf(Bs[(ks + c) * GSTR + nbase]);
                unsigned b1 = f2tf(Bs[(ks + c + 4) * GSTR + nbase]);
#pragma unroll
                for (int mf = 0; mf < 4; mf++)
                    mma_tf32(A.c[mf][nf], af[mf][0], af[mf][1], af[mf][2], af[mf][3], b0, b1);
            }
        }
    }
}

// QKV projection: z picks (input, weight, output); scatter to [B,H,T,DK]
__global__ void __launch_bounds__(256) gemm_qkv_kernel(
    const float* __restrict__ q_in, const float* __restrict__ k_in,
    const float* __restrict__ v_in, const float* __restrict__ Wq,
    const float* __restrict__ Wk,   const float* __restrict__ Wv)
{
    __shared__ float As[32 * GSTR];
    __shared__ float Bs[32 * GSTR];

    const int z = blockIdx.z;
    const float* X = (z == 0) ? q_in : (z == 1) ? k_in : v_in;
    const float* W = (z == 0) ? Wq   : (z == 1) ? Wk   : Wv;
    float* outp    = (z == 0) ? g_Q  : (z == 1) ? g_K  : g_V;

    const int m0 = blockIdx.x * 128, n0 = blockIdx.y * 128;
    GemmAcc A;
    gemm_tf32_body(X, W, m0, n0, As, Bs, A);

    const int lane = threadIdx.x & 31, wid = threadIdx.x >> 5;
    const int wm = (wid & 1) * 64, wn = (wid >> 1) * 32;
    const int g = lane >> 2, c = lane & 3;

#pragma unroll
    for (int mf = 0; mf < 4; mf++) {
        int row = m0 + wm + mf * 16 + g;
#pragma unroll
        for (int nf = 0; nf < 4; nf++) {
            int col = n0 + wn + nf * 8 + 2 * c;
            int h = col >> 7, dk = col & 127;
            {
                int b = row >> 11, t = row & 2047;
                float* p = outp + ((size_t)(b * HH + h) * TT + t) * DKK + dk;
                *(float2*)p = make_float2(A.c[mf][nf][0], A.c[mf][nf][1]);
            }
            {
                int row2 = row + 8;
                int b = row2 >> 11, t = row2 & 2047;
                float* p = outp + ((size_t)(b * HH + h) * TT + t) * DKK + dk;
                *(float2*)p = make_float2(A.c[mf][nf][2], A.c[mf][nf][3]);
            }
        }
    }
}

// Output projection: out = AO @ Wo^T + bo
__global__ void __launch_bounds__(256) gemm_out_kernel(
    const float* __restrict__ Wo, const float* __restrict__ bo,
    float* __restrict__ out)
{
    __shared__ float As[32 * GSTR];
    __shared__ float Bs[32 * GSTR];

    const int m0 = blockIdx.x * 128, n0 = blockIdx.y * 128;
    GemmAcc A;
    gemm_tf32_body(g_AO, Wo, m0, n0, As, Bs, A);

    const int lane = threadIdx.x & 31, wid = threadIdx.x >> 5;
    const int wm = (wid & 1) * 64, wn = (wid >> 1) * 32;
    const int g = lane >> 2, c = lane & 3;

#pragma unroll
    for (int mf = 0; mf < 4; mf++) {
        int row = m0 + wm + mf * 16 + g;
#pragma unroll
        for (int nf = 0; nf < 4; nf++) {
            int col = n0 + wn + nf * 8 + 2 * c;
            float2 bias = *(const float2*)(bo + col);
            *(float2*)(out + (size_t)row * DD + col) =
                make_float2(A.c[mf][nf][0] + bias.x, A.c[mf][nf][1] + bias.y);
            *(float2*)(out + (size_t)(row + 8) * DD + col) =
                make_float2(A.c[mf][nf][2] + bias.x, A.c[mf][nf][3] + bias.y);
        }
    }
}

// ---------------------------------------------------------------------------
// rel_bias transpose [B,Tq,Tk,H] -> [B,H,Tq,Tk], float4-coalesced both sides
// CTA = (k-chunk 256, q, b)
// ---------------------------------------------------------------------------
__global__ void __launch_bounds__(256) bias_transpose_kernel(const float* __restrict__ rb)
{
    __shared__ float sm[8][257];
    const int b = blockIdx.z, q = blockIdx.y, kc = blockIdx.x * 256;
    const int k = threadIdx.x;

    const float* src = rb + ((size_t)(b * TT + q) * TT + kc + k) * HH;
    float4 v0 = *(const float4*)(src);
    float4 v1 = *(const float4*)(src + 4);
    sm[0][k] = v0.x; sm[1][k] = v0.y; sm[2][k] = v0.z; sm[3][k] = v0.w;
    sm[4][k] = v1.x; sm[5][k] = v1.y; sm[6][k] = v1.z; sm[7][k] = v1.w;
    __syncthreads();
#pragma unroll
    for (int h = 0; h < HH; h++)
        g_biasT[((size_t)(b * HH + h) * TT + q) * TT + kc + k] = sm[h][k];
}

// ---------------------------------------------------------------------------
// Flash attention, TF32 mma. CTA = 128 q rows x (b,h). 8 warps, 16 q rows each.
// Q fragments register-resident for the whole CTA. S accum initialized with bias.
// ---------------------------------------------------------------------------
#define KSTR 132   // Ks row stride: frag banks (4g+c) conflict-free
#define VSTR 136   // Vs row stride: frag banks (8c+g) conflict-free
#define PSTR 68    // Ps row stride

__global__ void __launch_bounds__(256) attn_tf32_kernel(const int* __restrict__ is_causal_p)
{
    extern __shared__ float smn[];
    float* Ks = smn;                   // [64][KSTR] token-major
    float* Vs = Ks + 64 * KSTR;        // [64][VSTR] token-major
    float* Ps = Vs + 64 * VSTR;        // [128][PSTR]

    const int q0 = ((int)gridDim.x - 1 - (int)blockIdx.x) * 128;  // long CTAs first
    const int h = blockIdx.y, b = blockIdx.z;
    const int tid = threadIdx.x, lane = tid & 31, w = tid >> 5;
    const int g = lane >> 2, c = lane & 3;
    const bool causal = (is_causal_p[0] != 0);

    const float* Qg = g_Q + (size_t)(b * HH + h) * TT * DKK;
    const float* Kg = g_K + (size_t)(b * HH + h) * TT * DKK;
    const float* Vg = g_V + (size_t)(b * HH + h) * TT * DKK;
    const float* Bg = g_biasT + (size_t)(b * HH + h) * TT * TT;

    const float qscale = 0.08838834764831845f;   // 1/sqrt(128)
    const int r0 = q0 + w * 16 + g;               // global q row (first of pair)

    // Q fragments (scaled), reused for every k-tile
    unsigned qa[16][4];
#pragma unroll
    for (int ks = 0; ks < 16; ks++) {
        const float* p0 = Qg + (size_t)r0 * DKK + ks * 8 + c;
        const float* p1 = p0 + 8 * DKK;
        qa[ks][0] = f2tf(p0[0] * qscale);
        qa[ks][1] = f2tf(p1[0] * qscale);
        qa[ks][2] = f2tf(p0[4] * qscale);
        qa[ks][3] = f2tf(p1[4] * qscale);
    }

    float o[16][4];
#pragma unroll
    for (int nf = 0; nf < 16; nf++)
#pragma unroll
        for (int r = 0; r < 4; r++) o[nf][r] = 0.0f;
    float mi[2] = {-1e30f, -1e30f}, li[2] = {0.0f, 0.0f};

    const int ntiles = causal ? (q0 / 64 + 2) : (TT / 64);

    for (int kt = 0; kt < ntiles; kt++) {
        const int k0 = kt * 64;

        // Load K,V tiles (float4, coalesced)
        {
            const int tok = tid >> 5;
            const int d4  = (tid & 31) * 4;
#pragma unroll
            for (int it = 0; it < 8; it++) {
                int tk = tok + it * 8;
                *(float4*)(Ks + tk * KSTR + d4) = *(const float4*)(Kg + (size_t)(k0 + tk) * DKK + d4);
                *(float4*)(Vs + tk * VSTR + d4) = *(const float4*)(Vg + (size_t)(k0 + tk) * DKK + d4);
            }
        }
        __syncthreads();

        // S accum initialized with bias
        float s[8][4];
#pragma unroll
        for (int nf = 0; nf < 8; nf++) {
            const float* bp = Bg + (size_t)r0 * TT + k0 + nf * 8 + 2 * c;
            float2 b01 = *(const float2*)bp;
            float2 b23 = *(const float2*)(bp + (size_t)8 * TT);
            s[nf][0] = b01.x; s[nf][1] = b01.y; s[nf][2] = b23.x; s[nf][3] = b23.y;
        }

        // S += (Q*scale) K^T
#pragma unroll
        for (int ks = 0; ks < 16; ks++) {
#pragma unroll
            for (int nf = 0; nf < 8; nf++) {
                const float* kp = Ks + (nf * 8 + g) * KSTR + ks * 8 + c;
                unsigned b0 = f2tf(kp[0]);
                unsigned b1 = f2tf(kp[4]);
                mma_tf32(s[nf], qa[ks][0], qa[ks][1], qa[ks][2], qa[ks][3], b0, b1);
            }
        }

        // Causal mask (only tiles crossing the diagonal for this warp)
        if (causal && k0 + 63 > q0 + w * 16) {
#pragma unroll
            for (int nf = 0; nf < 8; nf++) {
                int col = k0 + nf * 8 + 2 * c;
                if (col     > r0)     s[nf][0] = -1e30f;
                if (col + 1 > r0)     s[nf][1] = -1e30f;
                if (col     > r0 + 8) s[nf][2] = -1e30f;
                if (col + 1 > r0 + 8) s[nf][3] = -1e30f;
            }
        }

        // Online softmax (row pair {r0, r0+8}); quad reduce via xor 1,2
#pragma unroll
        for (int r = 0; r < 2; r++) {
            const int i0 = 2 * r, i1 = 2 * r + 1;
            float rmax = -1e30f;
#pragma unroll
            for (int nf = 0; nf < 8; nf++)
                rmax = fmaxf(rmax, fmaxf(s[nf][i0], s[nf][i1]));
            rmax = fmaxf(rmax, __shfl_xor_sync(0xffffffffu, rmax, 1));
            rmax = fmaxf(rmax, __shfl_xor_sync(0xffffffffu, rmax, 2));
            float mnew = fmaxf(mi[r], rmax);
            float corr = __expf(mi[r] - mnew);
            float psum = 0.0f;
#pragma unroll
            for (int nf = 0; nf < 8; nf++) {
                float p0 = __expf(s[nf][i0] - mnew);
                float p1 = __expf(s[nf][i1] - mnew);
                s[nf][i0] = p0; s[nf][i1] = p1;
                psum += p0 + p1;
            }
            psum += __shfl_xor_sync(0xffffffffu, psum, 1);
            psum += __shfl_xor_sync(0xffffffffu, psum, 2);
            li[r] = li[r] * corr + psum;
            mi[r] = mnew;
#pragma unroll
            for (int nf = 0; nf < 16; nf++) { o[nf][i0] *= corr; o[nf][i1] *= corr; }
        }

        // Re-layout P through per-warp smem (C-frag -> A-frag)
#pragma unroll
        for (int nf = 0; nf < 8; nf++) {
            *(float2*)(Ps + (w * 16 + g) * PSTR + nf * 8 + 2 * c)     = make_float2(s[nf][0], s[nf][1]);
            *(float2*)(Ps + (w * 16 + g + 8) * PSTR + nf * 8 + 2 * c) = make_float2(s[nf][2], s[nf][3]);
        }
        __syncwarp();

        // O += P @ V
#pragma unroll
        for (int ks = 0; ks < 8; ks++) {
            const float* pp0 = Ps + (w * 16 + g) * PSTR + ks * 8 + c;
            const float* pp1 = Ps + (w * 16 + g + 8) * PSTR + ks * 8 + c;
            unsigned a0 = f2tf(pp0[0]);
            unsigned a1 = f2tf(pp1[0]);
            unsigned a2 = f2tf(pp0[4]);
            unsigned a3 = f2tf(pp1[4]);
#pragma unroll
            for (int nf = 0; nf < 16; nf++) {
                const float* vp = Vs + (ks * 8 + c) * VSTR + nf * 8 + g;
                unsigned b0 = f2tf(vp[0]);
                unsigned b1 = f2tf(vp[4 * VSTR]);
                mma_tf32(o[nf], a0, a1, a2, a3, b0, b1);
            }
        }
        __syncthreads();
    }

    // Epilogue: normalize, write [B,T,D]
    const float inv0 = 1.0f / li[0], inv1 = 1.0f / li[1];
    float* dst0 = g_AO + ((size_t)(b * TT + r0) * DD) + h * DKK;
    float* dst1 = dst0 + (size_t)8 * DD;
#pragma unroll
    for (int nf = 0; nf < 16; nf++) {
        int col = nf * 8 + 2 * c;
        *(float2*)(dst0 + col) = make_float2(o[nf][0] * inv0, o[nf][1] * inv0);
        *(float2*)(dst1 + col) = make_float2(o[nf][2] * inv1, o[nf][3] * inv1);
    }
}

// ---------------------------------------------------------------------------
// Launcher. Inputs: 0 query, 1 key, 2 value, 3 mask(all-false, unused),
// 4 rel_bias, 5 Wq, 6 Wk, 7 Wv, 8 Wo, 9 bo, 10 is_causal
// ---------------------------------------------------------------------------
extern "C" void kernel_launch(void* const* d_in, const int* in_sizes, int n_in,
                              void* d_out, int out_size)
{
    (void)in_sizes; (void)n_in; (void)out_size;
    const float* query    = (const float*)d_in[0];
    const float* key      = (const float*)d_in[1];
    const float* value    = (const float*)d_in[2];
    const float* rel_bias = (const float*)d_in[4];
    const float* Wq       = (const float*)d_in[5];
    const float* Wk       = (const float*)d_in[6];
    const float* Wv       = (const float*)d_in[7];
    const float* Wo       = (const float*)d_in[8];
    const float* bo       = (const float*)d_in[9];
    const int* is_causal  = (const int*)d_in[10];
    float* out            = (float*)d_out;

    // 1) QKV projections (TF32 mma, z-fused)
    gemm_qkv_kernel<<<dim3(MM / 128, DD / 128, 3), 256>>>(query, key, value, Wq, Wk, Wv);

    // 2) Bias transpose (coalesced)
    bias_transpose_kernel<<<dim3(TT / 256, TT, BB), 256>>>(rel_bias);

    // 3) Flash attention (TF32 mma)
    const int attn_smem = (64 * KSTR + 64 * VSTR + 128 * PSTR) * (int)sizeof(float); // 103424
    cudaFuncSetAttribute(attn_tf32_kernel, cudaFuncAttributeMaxDynamicSharedMemorySize, attn_smem);
    attn_tf32_kernel<<<dim3(TT / 128, HH, BB), 256, attn_smem>>>(is_causal);

    // 4) Output projection + bias (TF32 mma)
    gemm_out_kernel<<<dim3(MM / 128, DD / 128), 256>>>(Wo, bo, out);
}

// round 6
// speedup vs baseline: 4.2178x; 1.5409x over previous
#include <cuda_runtime.h>
#include <cuda_fp16.h>

// Problem constants
#define BB   2
#define TT   2048
#define DD   1024
#define HH   8
#define DKK  128
#define MM   (BB*TT)

// ---------------------------------------------------------------------------
// Scratch (device globals — no allocations allowed). All intermediates fp16.
// ---------------------------------------------------------------------------
__device__ __half g_Qh[(size_t)BB*HH*TT*DKK];      // 8 MB (pre-scaled by 1/sqrt(dk))
__device__ __half g_Kh[(size_t)BB*HH*TT*DKK];      // 8 MB
__device__ __half g_Vh[(size_t)BB*HH*TT*DKK];      // 8 MB
__device__ __half g_AOh[(size_t)BB*TT*DD];         // 8 MB
__device__ __half g_biasTh[(size_t)BB*HH*TT*TT];   // [B,H,Tq,Tk] 128 MB

// ---------------------------------------------------------------------------
// mma / ldmatrix helpers
// ---------------------------------------------------------------------------
__device__ __forceinline__ void ldsm4(unsigned r[4], const __half* p) {
    unsigned a = (unsigned)__cvta_generic_to_shared((void*)p);
    asm volatile("ldmatrix.sync.aligned.m8n8.x4.shared.b16 {%0,%1,%2,%3}, [%4];"
                 : "=r"(r[0]), "=r"(r[1]), "=r"(r[2]), "=r"(r[3]) : "r"(a));
}
__device__ __forceinline__ void ldsm4t(unsigned r[4], const __half* p) {
    unsigned a = (unsigned)__cvta_generic_to_shared((void*)p);
    asm volatile("ldmatrix.sync.aligned.m8n8.x4.trans.shared.b16 {%0,%1,%2,%3}, [%4];"
                 : "=r"(r[0]), "=r"(r[1]), "=r"(r[2]), "=r"(r[3]) : "r"(a));
}
__device__ __forceinline__ void mma16(float c[4], const unsigned a[4],
                                      unsigned b0, unsigned b1) {
    asm volatile(
        "mma.sync.aligned.m16n8k16.row.col.f32.f16.f16.f32 "
        "{%0,%1,%2,%3},{%4,%5,%6,%7},{%8,%9},{%0,%1,%2,%3};"
        : "+f"(c[0]), "+f"(c[1]), "+f"(c[2]), "+f"(c[3])
        : "r"(a[0]), "r"(a[1]), "r"(a[2]), "r"(a[3]), "r"(b0), "r"(b1));
}
__device__ __forceinline__ __half2 h2(float x, float y) { return __floats2half2_rn(x, y); }

// ---------------------------------------------------------------------------
// fp16 GEMM core: out[m,n] = sum_k X[m,k] * W[n,k]
// CTA 128x128, BK=32, 8 warps (2m x 4n), warp tile 64x32, mma m16n8k16.
// smem [row][k] stride 40 halves.
// ---------------------------------------------------------------------------
#define GSTRH 40

template<bool AHALF>
__device__ __forceinline__ void gemm16_body(
    const float* __restrict__ Xf, const __half* __restrict__ Xh,
    const float* __restrict__ W,
    int m0, int n0, __half* As, __half* Bs, float acc[4][4][4])
{
    const int tid = threadIdx.x;
    const int lane = tid & 31, wid = tid >> 5;
    const int wm = (wid & 1) * 64, wn = (wid >> 1) * 32;
    const int lm = tid & 127, kq = (tid >> 7) * 16;   // each thread: 16 k-values of one row

#pragma unroll
    for (int mf = 0; mf < 4; mf++)
#pragma unroll
        for (int nf = 0; nf < 4; nf++)
#pragma unroll
            for (int r = 0; r < 4; r++) acc[mf][nf][r] = 0.0f;

    float4 fw[4], fa[4];
    uint4 ha[2];                                       // 16 halves = 32 bytes

    // prefetch kt = 0
    {
        const float* wp = W + (size_t)(n0 + lm) * DD + kq;
#pragma unroll
        for (int i = 0; i < 4; i++) fw[i] = ((const float4*)wp)[i];
        if (AHALF) {
            const uint4* xp = (const uint4*)(Xh + (size_t)(m0 + lm) * DD + kq);
            ha[0] = xp[0]; ha[1] = xp[1];
        } else {
            const float* xp = Xf + (size_t)(m0 + lm) * DD + kq;
#pragma unroll
            for (int i = 0; i < 4; i++) fa[i] = ((const float4*)xp)[i];
        }
    }

    for (int kt = 0; kt < DD; kt += 32) {
        __syncthreads();
        {
            __half2* ap = (__half2*)(As + lm * GSTRH + kq);
            __half2* bp = (__half2*)(Bs + lm * GSTRH + kq);
            if (AHALF) {
                ((uint4*)ap)[0] = ha[0];
                ((uint4*)ap)[1] = ha[1];
            } else {
#pragma unroll
                for (int i = 0; i < 4; i++) {
                    ap[2 * i]     = h2(fa[i].x, fa[i].y);
                    ap[2 * i + 1] = h2(fa[i].z, fa[i].w);
                }
            }
#pragma unroll
            for (int i = 0; i < 4; i++) {
                bp[2 * i]     = h2(fw[i].x, fw[i].y);
                bp[2 * i + 1] = h2(fw[i].z, fw[i].w);
            }
        }
        __syncthreads();

        if (kt + 32 < DD) {
            const float* wp = W + (size_t)(n0 + lm) * DD + kt + 32 + kq;
#pragma unroll
            for (int i = 0; i < 4; i++) fw[i] = ((const float4*)wp)[i];
            if (AHALF) {
                const uint4* xp = (const uint4*)(Xh + (size_t)(m0 + lm) * DD + kt + 32 + kq);
                ha[0] = xp[0]; ha[1] = xp[1];
            } else {
                const float* xp = Xf + (size_t)(m0 + lm) * DD + kt + 32 + kq;
#pragma unroll
                for (int i = 0; i < 4; i++) fa[i] = ((const float4*)xp)[i];
            }
        }

#pragma unroll
        for (int ks = 0; ks < 2; ks++) {
            unsigned af[4][4];
#pragma unroll
            for (int mf = 0; mf < 4; mf++) {
                const __half* p = As + (wm + mf * 16 + ((lane >> 3) & 1) * 8 + (lane & 7)) * GSTRH
                                     + ks * 16 + (lane >> 4) * 8;
                ldsm4(af[mf], p);
            }
#pragma unroll
            for (int nfp = 0; nfp < 2; nfp++) {
                unsigned bf[4];
                const __half* p = Bs + (wn + nfp * 16 + (lane >> 4) * 8 + (lane & 7)) * GSTRH
                                     + ks * 16 + ((lane >> 3) & 1) * 8;
                ldsm4(bf, p);
#pragma unroll
                for (int mf = 0; mf < 4; mf++) {
                    mma16(acc[mf][nfp * 2],     af[mf], bf[0], bf[1]);
                    mma16(acc[mf][nfp * 2 + 1], af[mf], bf[2], bf[3]);
                }
            }
        }
    }
}

// QKV projection: z picks (input, weight, output); fp16 scatter to [B,H,T,DK].
// Q pre-scaled by 1/sqrt(dk).
__global__ void __launch_bounds__(256) gemm_qkv_kernel(
    const float* __restrict__ q_in, const float* __restrict__ k_in,
    const float* __restrict__ v_in, const float* __restrict__ Wq,
    const float* __restrict__ Wk,   const float* __restrict__ Wv)
{
    __shared__ __align__(16) __half As[128 * GSTRH];
    __shared__ __align__(16) __half Bs[128 * GSTRH];

    const int z = blockIdx.z;
    const float* X = (z == 0) ? q_in : (z == 1) ? k_in : v_in;
    const float* W = (z == 0) ? Wq   : (z == 1) ? Wk   : Wv;
    __half* outp   = (z == 0) ? g_Qh : (z == 1) ? g_Kh : g_Vh;
    const float sc = (z == 0) ? 0.08838834764831845f : 1.0f;

    const int m0 = blockIdx.x * 128, n0 = blockIdx.y * 128;
    float acc[4][4][4];
    gemm16_body<false>(X, nullptr, W, m0, n0, As, Bs, acc);

    const int lane = threadIdx.x & 31, wid = threadIdx.x >> 5;
    const int wm = (wid & 1) * 64, wn = (wid >> 1) * 32;
    const int g = lane >> 2, c = lane & 3;

#pragma unroll
    for (int mf = 0; mf < 4; mf++) {
        int row = m0 + wm + mf * 16 + g;
#pragma unroll
        for (int nf = 0; nf < 4; nf++) {
            int col = n0 + wn + nf * 8 + 2 * c;
            int h = col >> 7, dk = col & 127;
            {
                int b = row >> 11, t = row & 2047;
                *(__half2*)(outp + ((size_t)(b * HH + h) * TT + t) * DKK + dk) =
                    h2(acc[mf][nf][0] * sc, acc[mf][nf][1] * sc);
            }
            {
                int row2 = row + 8;
                int b = row2 >> 11, t = row2 & 2047;
                *(__half2*)(outp + ((size_t)(b * HH + h) * TT + t) * DKK + dk) =
                    h2(acc[mf][nf][2] * sc, acc[mf][nf][3] * sc);
            }
        }
    }
}

// Output projection: out = AO @ Wo^T + bo  (fp32 output)
__global__ void __launch_bounds__(256) gemm_out_kernel(
    const float* __restrict__ Wo, const float* __restrict__ bo,
    float* __restrict__ out)
{
    __shared__ __align__(16) __half As[128 * GSTRH];
    __shared__ __align__(16) __half Bs[128 * GSTRH];

    const int m0 = blockIdx.x * 128, n0 = blockIdx.y * 128;
    float acc[4][4][4];
    gemm16_body<true>(nullptr, g_AOh, Wo, m0, n0, As, Bs, acc);

    const int lane = threadIdx.x & 31, wid = threadIdx.x >> 5;
    const int wm = (wid & 1) * 64, wn = (wid >> 1) * 32;
    const int g = lane >> 2, c = lane & 3;

#pragma unroll
    for (int mf = 0; mf < 4; mf++) {
        int row = m0 + wm + mf * 16 + g;
#pragma unroll
        for (int nf = 0; nf < 4; nf++) {
            int col = n0 + wn + nf * 8 + 2 * c;
            float2 bias = *(const float2*)(bo + col);
            *(float2*)(out + (size_t)row * DD + col) =
                make_float2(acc[mf][nf][0] + bias.x, acc[mf][nf][1] + bias.y);
            *(float2*)(out + (size_t)(row + 8) * DD + col) =
                make_float2(acc[mf][nf][2] + bias.x, acc[mf][nf][3] + bias.y);
        }
    }
}

// ---------------------------------------------------------------------------
// rel_bias transpose [B,Tq,Tk,H] fp32 -> [B,H,Tq,Tk] fp16
// ---------------------------------------------------------------------------
__global__ void __launch_bounds__(256) bias_transpose_kernel(const float* __restrict__ rb)
{
    __shared__ __half sm[8][264];
    const int b = blockIdx.z, q = blockIdx.y, kc = blockIdx.x * 256;
    const int k = threadIdx.x;

    const float* src = rb + ((size_t)(b * TT + q) * TT + kc + k) * HH;
    float4 v0 = *(const float4*)(src);
    float4 v1 = *(const float4*)(src + 4);
    sm[0][k] = __float2half(v0.x); sm[1][k] = __float2half(v0.y);
    sm[2][k] = __float2half(v0.z); sm[3][k] = __float2half(v0.w);
    sm[4][k] = __float2half(v1.x); sm[5][k] = __float2half(v1.y);
    sm[6][k] = __float2half(v1.z); sm[7][k] = __float2half(v1.w);
    __syncthreads();
#pragma unroll
    for (int h = 0; h < HH; h++)
        g_biasTh[((size_t)(b * HH + h) * TT + q) * TT + kc + k] = sm[h][k];
}

// ---------------------------------------------------------------------------
// Flash attention, fp16 mma + ldmatrix. CTA = 128 q rows x (b,h), 8 warps.
// ---------------------------------------------------------------------------
#define AKSTR 136   // K/V smem stride (halves)
#define APSTR 72    // P smem stride (halves)

__global__ void __launch_bounds__(256) attn_h_kernel(const int* __restrict__ is_causal_p)
{
    extern __shared__ __half smh[];
    __half* Ks = smh;                    // [64][AKSTR]
    __half* Vs = Ks + 64 * AKSTR;        // [64][AKSTR]
    __half* Ps = Vs + 64 * AKSTR;        // [128][APSTR]

    const int q0 = ((int)gridDim.x - 1 - (int)blockIdx.x) * 128;  // long CTAs first
    const int h = blockIdx.y, b = blockIdx.z;
    const int tid = threadIdx.x, lane = tid & 31, w = tid >> 5;
    const int g = lane >> 2, c = lane & 3;
    const bool causal = (is_causal_p[0] != 0);

    const __half* Qg = g_Qh + (size_t)(b * HH + h) * TT * DKK;
    const __half* Kg = g_Kh + (size_t)(b * HH + h) * TT * DKK;
    const __half* Vg = g_Vh + (size_t)(b * HH + h) * TT * DKK;
    const __half* Bg = g_biasTh + (size_t)(b * HH + h) * TT * TT;

    const int r0 = q0 + w * 16 + g;   // first of this thread's q-row pair

    // Q A-fragments, register-resident (Q already scaled by 1/sqrt(dk))
    unsigned qa[8][4];
#pragma unroll
    for (int ks = 0; ks < 8; ks++) {
        const __half* p = Qg + (size_t)r0 * DKK + ks * 16 + 2 * c;
        qa[ks][0] = *(const unsigned*)(p);
        qa[ks][1] = *(const unsigned*)(p + 8 * DKK);
        qa[ks][2] = *(const unsigned*)(p + 8);
        qa[ks][3] = *(const unsigned*)(p + 8 * DKK + 8);
    }

    float o[16][4];
#pragma unroll
    for (int nf = 0; nf < 16; nf++)
#pragma unroll
        for (int r = 0; r < 4; r++) o[nf][r] = 0.0f;
    float mi[2] = {-1e30f, -1e30f}, li[2] = {0.0f, 0.0f};

    const int ntiles = causal ? (q0 / 64 + 2) : (TT / 64);

    for (int kt = 0; kt < ntiles; kt++) {
        const int k0 = kt * 64;

        // Stage K,V: 64 rows x 128 halves each; thread copies 4x uint4 (32 halves)
        {
            const int row = tid >> 2;
            const int qu  = (tid & 3) * 32;
            const __half* kg = Kg + (size_t)(k0 + row) * DKK + qu;
            const __half* vg = Vg + (size_t)(k0 + row) * DKK + qu;
            __half* ksp = Ks + row * AKSTR + qu;
            __half* vsp = Vs + row * AKSTR + qu;
#pragma unroll
            for (int j = 0; j < 4; j++) {
                *(uint4*)(ksp + 8 * j) = *(const uint4*)(kg + 8 * j);
                *(uint4*)(vsp + 8 * j) = *(const uint4*)(vg + 8 * j);
            }
        }
        __syncthreads();

        // S accum initialized with bias
        float s[8][4];
#pragma unroll
        for (int nf = 0; nf < 8; nf++) {
            const __half* bp = Bg + (size_t)r0 * TT + k0 + nf * 8 + 2 * c;
            float2 b01 = __half22float2(*(const __half2*)bp);
            float2 b23 = __half22float2(*(const __half2*)(bp + (size_t)8 * TT));
            s[nf][0] = b01.x; s[nf][1] = b01.y; s[nf][2] = b23.x; s[nf][3] = b23.y;
        }

        // S += Q K^T
#pragma unroll
        for (int ks = 0; ks < 8; ks++) {
#pragma unroll
            for (int nfp = 0; nfp < 4; nfp++) {
                unsigned bf[4];
                const __half* p = Ks + (nfp * 16 + (lane >> 4) * 8 + (lane & 7)) * AKSTR
                                     + ks * 16 + ((lane >> 3) & 1) * 8;
                ldsm4(bf, p);
                mma16(s[nfp * 2],     qa[ks], bf[0], bf[1]);
                mma16(s[nfp * 2 + 1], qa[ks], bf[2], bf[3]);
            }
        }

        // Causal mask (only diagonal-crossing tiles for this warp)
        if (causal && k0 + 63 > q0 + w * 16) {
#pragma unroll
            for (int nf = 0; nf < 8; nf++) {
                int col = k0 + nf * 8 + 2 * c;
                if (col     > r0)     s[nf][0] = -1e30f;
                if (col + 1 > r0)     s[nf][1] = -1e30f;
                if (col     > r0 + 8) s[nf][2] = -1e30f;
                if (col + 1 > r0 + 8) s[nf][3] = -1e30f;
            }
        }

        // Online softmax (row pair {r0, r0+8}); quad reduce via xor 1,2
#pragma unroll
        for (int r = 0; r < 2; r++) {
            const int i0 = 2 * r, i1 = 2 * r + 1;
            float rmax = -1e30f;
#pragma unroll
            for (int nf = 0; nf < 8; nf++)
                rmax = fmaxf(rmax, fmaxf(s[nf][i0], s[nf][i1]));
            rmax = fmaxf(rmax, __shfl_xor_sync(0xffffffffu, rmax, 1));
            rmax = fmaxf(rmax, __shfl_xor_sync(0xffffffffu, rmax, 2));
            float mnew = fmaxf(mi[r], rmax);
            float corr = __expf(mi[r] - mnew);
            float psum = 0.0f;
#pragma unroll
            for (int nf = 0; nf < 8; nf++) {
                float p0 = __expf(s[nf][i0] - mnew);
                float p1 = __expf(s[nf][i1] - mnew);
                s[nf][i0] = p0; s[nf][i1] = p1;
                psum += p0 + p1;
            }
            psum += __shfl_xor_sync(0xffffffffu, psum, 1);
            psum += __shfl_xor_sync(0xffffffffu, psum, 2);
            li[r] = li[r] * corr + psum;
            mi[r] = mnew;
#pragma unroll
            for (int nf = 0; nf < 16; nf++) { o[nf][i0] *= corr; o[nf][i1] *= corr; }
        }

        // P -> per-warp smem as fp16 (C-frag -> A-frag re-layout)
#pragma unroll
        for (int nf = 0; nf < 8; nf++) {
            *(__half2*)(Ps + (w * 16 + g) * APSTR + nf * 8 + 2 * c)     = h2(s[nf][0], s[nf][1]);
            *(__half2*)(Ps + (w * 16 + g + 8) * APSTR + nf * 8 + 2 * c) = h2(s[nf][2], s[nf][3]);
        }
        __syncwarp();

        // O += P @ V   (B frags via ldmatrix.trans on [tok][dk] V tile)
#pragma unroll
        for (int kst = 0; kst < 4; kst++) {
            unsigned pa[4];
            const __half* pp = Ps + (w * 16 + ((lane >> 3) & 1) * 8 + (lane & 7)) * APSTR
                                  + kst * 16 + (lane >> 4) * 8;
            ldsm4(pa, pp);
#pragma unroll
            for (int nfp = 0; nfp < 8; nfp++) {
                unsigned vb[4];
                const __half* vp = Vs + (kst * 16 + ((lane >> 3) & 1) * 8 + (lane & 7)) * AKSTR
                                      + nfp * 16 + (lane >> 4) * 8;
                ldsm4t(vb, vp);
                mma16(o[nfp * 2],     pa, vb[0], vb[1]);
                mma16(o[nfp * 2 + 1], pa, vb[2], vb[3]);
            }
        }
        __syncthreads();
    }

    // Epilogue: normalize, write fp16 AO in [B,T,D]
    const float inv0 = 1.0f / li[0], inv1 = 1.0f / li[1];
    __half* dst0 = g_AOh + ((size_t)(b * TT + r0) * DD) + h * DKK;
    __half* dst1 = dst0 + (size_t)8 * DD;
#pragma unroll
    for (int nf = 0; nf < 16; nf++) {
        int col = nf * 8 + 2 * c;
        *(__half2*)(dst0 + col) = h2(o[nf][0] * inv0, o[nf][1] * inv0);
        *(__half2*)(dst1 + col) = h2(o[nf][2] * inv1, o[nf][3] * inv1);
    }
}

// ---------------------------------------------------------------------------
// Launcher. Inputs: 0 query, 1 key, 2 value, 3 mask(all-false, unused),
// 4 rel_bias, 5 Wq, 6 Wk, 7 Wv, 8 Wo, 9 bo, 10 is_causal
// ---------------------------------------------------------------------------
extern "C" void kernel_launch(void* const* d_in, const int* in_sizes, int n_in,
                              void* d_out, int out_size)
{
    (void)in_sizes; (void)n_in; (void)out_size;
    const float* query    = (const float*)d_in[0];
    const float* key      = (const float*)d_in[1];
    const float* value    = (const float*)d_in[2];
    const float* rel_bias = (const float*)d_in[4];
    const float* Wq       = (const float*)d_in[5];
    const float* Wk       = (const float*)d_in[6];
    const float* Wv       = (const float*)d_in[7];
    const float* Wo       = (const float*)d_in[8];
    const float* bo       = (const float*)d_in[9];
    const int* is_causal  = (const int*)d_in[10];
    float* out            = (float*)d_out;

    // 1) QKV projections (fp16 mma, z-fused)
    gemm_qkv_kernel<<<dim3(MM / 128, DD / 128, 3), 256>>>(query, key, value, Wq, Wk, Wv);

    // 2) Bias transpose -> fp16
    bias_transpose_kernel<<<dim3(TT / 256, TT, BB), 256>>>(rel_bias);

    // 3) Flash attention (fp16 mma + ldmatrix)
    const int attn_smem = (2 * 64 * AKSTR + 128 * APSTR) * (int)sizeof(__half); // 53248 B
    cudaFuncSetAttribute(attn_h_kernel, cudaFuncAttributeMaxDynamicSharedMemorySize, attn_smem);
    attn_h_kernel<<<dim3(TT / 128, HH, BB), 256, attn_smem>>>(is_causal);

    // 4) Output projection + bias (fp16 mma, fp32 out)
    gemm_out_kernel<<<dim3(MM / 128, DD / 128), 256>>>(Wo, bo, out);
}

// round 7
// speedup vs baseline: 4.2939x; 1.0180x over previous
#include <cuda_runtime.h>
#include <cuda_fp16.h>

// Problem constants
#define BB   2
#define TT   2048
#define DD   1024
#define HH   8
#define DKK  128
#define MM   (BB*TT)

// ---------------------------------------------------------------------------
// Scratch (device globals — no allocations allowed). All intermediates fp16.
// ---------------------------------------------------------------------------
__device__ __half g_Qh[(size_t)BB*HH*TT*DKK];      // 8 MB (pre-scaled by 1/sqrt(dk))
__device__ __half g_Kh[(size_t)BB*HH*TT*DKK];      // 8 MB
__device__ __half g_Vh[(size_t)BB*HH*TT*DKK];      // 8 MB
__device__ __half g_AOh[(size_t)BB*TT*DD];         // 8 MB
__device__ __half g_biasTh[(size_t)BB*HH*TT*TT];   // [B,H,Tq,Tk] 128 MB

// ---------------------------------------------------------------------------
// mma / ldmatrix helpers
// ---------------------------------------------------------------------------
__device__ __forceinline__ void ldsm4(unsigned r[4], const __half* p) {
    unsigned a = (unsigned)__cvta_generic_to_shared((void*)p);
    asm volatile("ldmatrix.sync.aligned.m8n8.x4.shared.b16 {%0,%1,%2,%3}, [%4];"
                 : "=r"(r[0]), "=r"(r[1]), "=r"(r[2]), "=r"(r[3]) : "r"(a));
}
__device__ __forceinline__ void ldsm4t(unsigned r[4], const __half* p) {
    unsigned a = (unsigned)__cvta_generic_to_shared((void*)p);
    asm volatile("ldmatrix.sync.aligned.m8n8.x4.trans.shared.b16 {%0,%1,%2,%3}, [%4];"
                 : "=r"(r[0]), "=r"(r[1]), "=r"(r[2]), "=r"(r[3]) : "r"(a));
}
__device__ __forceinline__ void mma16(float c[4], const unsigned a[4],
                                      unsigned b0, unsigned b1) {
    asm volatile(
        "mma.sync.aligned.m16n8k16.row.col.f32.f16.f16.f32 "
        "{%0,%1,%2,%3},{%4,%5,%6,%7},{%8,%9},{%0,%1,%2,%3};"
        : "+f"(c[0]), "+f"(c[1]), "+f"(c[2]), "+f"(c[3])
        : "r"(a[0]), "r"(a[1]), "r"(a[2]), "r"(a[3]), "r"(b0), "r"(b1));
}
__device__ __forceinline__ __half2 h2(float x, float y) { return __floats2half2_rn(x, y); }

__device__ __forceinline__ unsigned packh2(float x, float y) {
    __half2 v = __floats2half2_rn(x, y);
    return *(unsigned*)&v;
}
__device__ __forceinline__ uint4 pack8(float4 a, float4 b) {
    uint4 u;
    u.x = packh2(a.x, a.y); u.y = packh2(a.z, a.w);
    u.z = packh2(b.x, b.y); u.w = packh2(b.z, b.w);
    return u;
}

// GEMM smem swizzle: tile [128 rows][32 halves], 4 chunks of 8 halves per row.
// addr(r,c) = r*32 + ((c ^ ((r>>1)&3)) << 3). Conflict-free for 16B staging
// stores and all ldmatrix phases.
#define GIDX(r, c) (((r) << 5) + ((((c) ^ (((r) >> 1) & 3))) << 3))

// Attention smem swizzle: tile [64 rows][128 halves], 16 chunks of 8 halves.
// s(r) = bit-reversed low-3 row bits; conflict-free for staging stores
// (lane-quad covers chunks {0,1,2,3}+4j) and ldsm / ldsm4t phases.
#define SATT(r) (((((r) & 1) << 2) | ((r) & 2) | (((r) >> 2) & 1)))
#define AIDX(r, c) (((r) << 7) + ((((c) ^ SATT((r) & 7))) << 3))

// ---------------------------------------------------------------------------
// fp16 GEMM core: out[m,n] = sum_k X[m,k] * W[n,k]
// CTA 128x128, BK=32, 8 warps (2m x 4n), warp tile 64x32, mma m16n8k16.
// ---------------------------------------------------------------------------
template<bool AHALF>
__device__ __forceinline__ void gemm16_body(
    const float* __restrict__ Xf, const __half* __restrict__ Xh,
    const float* __restrict__ W,
    int m0, int n0, __half* As, __half* Bs, float acc[4][4][4])
{
    const int tid = threadIdx.x;
    const int lane = tid & 31, wid = tid >> 5;
    const int wm = (wid & 1) * 64, wn = (wid >> 1) * 32;
    const int lm = tid & 127, kq = (tid >> 7) * 16;   // 16 k-values of one row
    const int c0 = kq >> 3;                            // chunk base: 0 or 2

#pragma unroll
    for (int mf = 0; mf < 4; mf++)
#pragma unroll
        for (int nf = 0; nf < 4; nf++)
#pragma unroll
            for (int r = 0; r < 4; r++) acc[mf][nf][r] = 0.0f;

    float4 fw[4], fa[4];
    uint4 ha[2];

    // prefetch kt = 0
    {
        const float* wp = W + (size_t)(n0 + lm) * DD + kq;
#pragma unroll
        for (int i = 0; i < 4; i++) fw[i] = ((const float4*)wp)[i];
        if (AHALF) {
            const uint4* xp = (const uint4*)(Xh + (size_t)(m0 + lm) * DD + kq);
            ha[0] = xp[0]; ha[1] = xp[1];
        } else {
            const float* xp = Xf + (size_t)(m0 + lm) * DD + kq;
#pragma unroll
            for (int i = 0; i < 4; i++) fa[i] = ((const float4*)xp)[i];
        }
    }

    for (int kt = 0; kt < DD; kt += 32) {
        __syncthreads();
        {
            // pack in registers, store 16B conflict-free
            uint4 a0, a1;
            if (AHALF) { a0 = ha[0]; a1 = ha[1]; }
            else       { a0 = pack8(fa[0], fa[1]); a1 = pack8(fa[2], fa[3]); }
            *(uint4*)(As + GIDX(lm, c0))     = a0;
            *(uint4*)(As + GIDX(lm, c0 + 1)) = a1;
            *(uint4*)(Bs + GIDX(lm, c0))     = pack8(fw[0], fw[1]);
            *(uint4*)(Bs + GIDX(lm, c0 + 1)) = pack8(fw[2], fw[3]);
        }
        __syncthreads();

        if (kt + 32 < DD) {
            const float* wp = W + (size_t)(n0 + lm) * DD + kt + 32 + kq;
#pragma unroll
            for (int i = 0; i < 4; i++) fw[i] = ((const float4*)wp)[i];
            if (AHALF) {
                const uint4* xp = (const uint4*)(Xh + (size_t)(m0 + lm) * DD + kt + 32 + kq);
                ha[0] = xp[0]; ha[1] = xp[1];
            } else {
                const float* xp = Xf + (size_t)(m0 + lm) * DD + kt + 32 + kq;
#pragma unroll
                for (int i = 0; i < 4; i++) fa[i] = ((const float4*)xp)[i];
            }
        }

#pragma unroll
        for (int ks = 0; ks < 2; ks++) {
            unsigned af[4][4];
#pragma unroll
            for (int mf = 0; mf < 4; mf++) {
                int rA = wm + mf * 16 + ((lane >> 3) & 1) * 8 + (lane & 7);
                int cA = 2 * ks + (lane >> 4);
                ldsm4(af[mf], As + GIDX(rA, cA));
            }
#pragma unroll
            for (int nfp = 0; nfp < 2; nfp++) {
                unsigned bf[4];
                int rB = wn + nfp * 16 + (lane >> 4) * 8 + (lane & 7);
                int cB = 2 * ks + ((lane >> 3) & 1);
                ldsm4(bf, Bs + GIDX(rB, cB));
#pragma unroll
                for (int mf = 0; mf < 4; mf++) {
                    mma16(acc[mf][nfp * 2],     af[mf], bf[0], bf[1]);
                    mma16(acc[mf][nfp * 2 + 1], af[mf], bf[2], bf[3]);
                }
            }
        }
    }
}

// QKV projection: z picks (input, weight, output); fp16 scatter to [B,H,T,DK].
// Q pre-scaled by 1/sqrt(dk).
__global__ void __launch_bounds__(256) gemm_qkv_kernel(
    const float* __restrict__ q_in, const float* __restrict__ k_in,
    const float* __restrict__ v_in, const float* __restrict__ Wq,
    const float* __restrict__ Wk,   const float* __restrict__ Wv)
{
    __shared__ __align__(16) __half As[128 * 32];
    __shared__ __align__(16) __half Bs[128 * 32];

    const int z = blockIdx.z;
    const float* X = (z == 0) ? q_in : (z == 1) ? k_in : v_in;
    const float* W = (z == 0) ? Wq   : (z == 1) ? Wk   : Wv;
    __half* outp   = (z == 0) ? g_Qh : (z == 1) ? g_Kh : g_Vh;
    const float sc = (z == 0) ? 0.08838834764831845f : 1.0f;

    const int m0 = blockIdx.x * 128, n0 = blockIdx.y * 128;
    float acc[4][4][4];
    gemm16_body<false>(X, nullptr, W, m0, n0, As, Bs, acc);

    const int lane = threadIdx.x & 31, wid = threadIdx.x >> 5;
    const int wm = (wid & 1) * 64, wn = (wid >> 1) * 32;
    const int g = lane >> 2, c = lane & 3;

#pragma unroll
    for (int mf = 0; mf < 4; mf++) {
        int row = m0 + wm + mf * 16 + g;
#pragma unroll
        for (int nf = 0; nf < 4; nf++) {
            int col = n0 + wn + nf * 8 + 2 * c;
            int h = col >> 7, dk = col & 127;
            {
                int b = row >> 11, t = row & 2047;
                *(__half2*)(outp + ((size_t)(b * HH + h) * TT + t) * DKK + dk) =
                    h2(acc[mf][nf][0] * sc, acc[mf][nf][1] * sc);
            }
            {
                int row2 = row + 8;
                int b = row2 >> 11, t = row2 & 2047;
                *(__half2*)(outp + ((size_t)(b * HH + h) * TT + t) * DKK + dk) =
                    h2(acc[mf][nf][2] * sc, acc[mf][nf][3] * sc);
            }
        }
    }
}

// Output projection: out = AO @ Wo^T + bo  (fp32 output)
__global__ void __launch_bounds__(256) gemm_out_kernel(
    const float* __restrict__ Wo, const float* __restrict__ bo,
    float* __restrict__ out)
{
    __shared__ __align__(16) __half As[128 * 32];
    __shared__ __align__(16) __half Bs[128 * 32];

    const int m0 = blockIdx.x * 128, n0 = blockIdx.y * 128;
    float acc[4][4][4];
    gemm16_body<true>(nullptr, g_AOh, Wo, m0, n0, As, Bs, acc);

    const int lane = threadIdx.x & 31, wid = threadIdx.x >> 5;
    const int wm = (wid & 1) * 64, wn = (wid >> 1) * 32;
    const int g = lane >> 2, c = lane & 3;

#pragma unroll
    for (int mf = 0; mf < 4; mf++) {
        int row = m0 + wm + mf * 16 + g;
#pragma unroll
        for (int nf = 0; nf < 4; nf++) {
            int col = n0 + wn + nf * 8 + 2 * c;
            float2 bias = *(const float2*)(bo + col);
            *(float2*)(out + (size_t)row * DD + col) =
                make_float2(acc[mf][nf][0] + bias.x, acc[mf][nf][1] + bias.y);
            *(float2*)(out + (size_t)(row + 8) * DD + col) =
                make_float2(acc[mf][nf][2] + bias.x, acc[mf][nf][3] + bias.y);
        }
    }
}

// ---------------------------------------------------------------------------
// rel_bias transpose [B,Tq,Tk,H] fp32 -> [B,H,Tq,Tk] fp16
// ---------------------------------------------------------------------------
__global__ void __launch_bounds__(256) bias_transpose_kernel(const float* __restrict__ rb)
{
    __shared__ __half sm[8][264];
    const int b = blockIdx.z, q = blockIdx.y, kc = blockIdx.x * 256;
    const int k = threadIdx.x;

    const float* src = rb + ((size_t)(b * TT + q) * TT + kc + k) * HH;
    float4 v0 = *(const float4*)(src);
    float4 v1 = *(const float4*)(src + 4);
    sm[0][k] = __float2half(v0.x); sm[1][k] = __float2half(v0.y);
    sm[2][k] = __float2half(v0.z); sm[3][k] = __float2half(v0.w);
    sm[4][k] = __float2half(v1.x); sm[5][k] = __float2half(v1.y);
    sm[6][k] = __float2half(v1.z); sm[7][k] = __float2half(v1.w);
    __syncthreads();
#pragma unroll
    for (int h = 0; h < HH; h++)
        g_biasTh[((size_t)(b * HH + h) * TT + q) * TT + kc + k] = sm[h][k];
}

// ---------------------------------------------------------------------------
// Flash attention, fp16 mma + ldmatrix. CTA = 128 q rows x (b,h), 8 warps.
// K/V tiles in swizzled [64][128] smem; P per-warp stride-72.
// ---------------------------------------------------------------------------
#define APSTR 72    // P smem stride (halves)

__global__ void __launch_bounds__(256) attn_h_kernel(const int* __restrict__ is_causal_p)
{
    extern __shared__ __half smh[];
    __half* Ks = smh;                    // [64][128] swizzled
    __half* Vs = Ks + 64 * 128;          // [64][128] swizzled
    __half* Ps = Vs + 64 * 128;          // [128][APSTR]

    const int q0 = ((int)gridDim.x - 1 - (int)blockIdx.x) * 128;  // long CTAs first
    const int h = blockIdx.y, b = blockIdx.z;
    const int tid = threadIdx.x, lane = tid & 31, w = tid >> 5;
    const int g = lane >> 2, c = lane & 3;
    const bool causal = (is_causal_p[0] != 0);

    const __half* Qg = g_Qh + (size_t)(b * HH + h) * TT * DKK;
    const __half* Kg = g_Kh + (size_t)(b * HH + h) * TT * DKK;
    const __half* Vg = g_Vh + (size_t)(b * HH + h) * TT * DKK;
    const __half* Bg = g_biasTh + (size_t)(b * HH + h) * TT * TT;

    const int r0 = q0 + w * 16 + g;   // first of this thread's q-row pair

    // Q A-fragments, register-resident (Q already scaled by 1/sqrt(dk))
    unsigned qa[8][4];
#pragma unroll
    for (int ks = 0; ks < 8; ks++) {
        const __half* p = Qg + (size_t)r0 * DKK + ks * 16 + 2 * c;
        qa[ks][0] = *(const unsigned*)(p);
        qa[ks][1] = *(const unsigned*)(p + 8 * DKK);
        qa[ks][2] = *(const unsigned*)(p + 8);
        qa[ks][3] = *(const unsigned*)(p + 8 * DKK + 8);
    }

    float o[16][4];
#pragma unroll
    for (int nf = 0; nf < 16; nf++)
#pragma unroll
        for (int r = 0; r < 4; r++) o[nf][r] = 0.0f;
    float mi[2] = {-1e30f, -1e30f}, li[2] = {0.0f, 0.0f};

    const int ntiles = causal ? (q0 / 64 + 2) : (TT / 64);

    // staging map: row = tid>>2, chunks (tid&3) + 4j  (gmem coalesced, smem
    // stores conflict-free under SATT swizzle)
    const int srow = tid >> 2;
    const int scb  = tid & 3;

    for (int kt = 0; kt < ntiles; kt++) {
        const int k0 = kt * 64;
        {
            const __half* kg = Kg + (size_t)(k0 + srow) * DKK + scb * 8;
            const __half* vg = Vg + (size_t)(k0 + srow) * DKK + scb * 8;
#pragma unroll
            for (int j = 0; j < 4; j++) {
                int ch = scb + 4 * j;
                *(uint4*)(Ks + AIDX(srow, ch)) = *(const uint4*)(kg + 32 * j);
                *(uint4*)(Vs + AIDX(srow, ch)) = *(const uint4*)(vg + 32 * j);
            }
        }
        __syncthreads();

        // S accum initialized with bias
        float s[8][4];
#pragma unroll
        for (int nf = 0; nf < 8; nf++) {
            const __half* bp = Bg + (size_t)r0 * TT + k0 + nf * 8 + 2 * c;
            float2 b01 = __half22float2(*(const __half2*)bp);
            float2 b23 = __half22float2(*(const __half2*)(bp + (size_t)8 * TT));
            s[nf][0] = b01.x; s[nf][1] = b01.y; s[nf][2] = b23.x; s[nf][3] = b23.y;
        }

        // S += Q K^T
#pragma unroll
        for (int ks = 0; ks < 8; ks++) {
#pragma unroll
            for (int nfp = 0; nfp < 4; nfp++) {
                unsigned bf[4];
                int rB = nfp * 16 + (lane >> 4) * 8 + (lane & 7);
                int cB = 2 * ks + ((lane >> 3) & 1);
                ldsm4(bf, Ks + AIDX(rB, cB));
                mma16(s[nfp * 2],     qa[ks], bf[0], bf[1]);
                mma16(s[nfp * 2 + 1], qa[ks], bf[2], bf[3]);
            }
        }

        // Causal mask (only diagonal-crossing tiles for this warp)
        if (causal && k0 + 63 > q0 + w * 16) {
#pragma unroll
            for (int nf = 0; nf < 8; nf++) {
                int col = k0 + nf * 8 + 2 * c;
                if (col     > r0)     s[nf][0] = -1e30f;
                if (col + 1 > r0)     s[nf][1] = -1e30f;
                if (col     > r0 + 8) s[nf][2] = -1e30f;
                if (col + 1 > r0 + 8) s[nf][3] = -1e30f;
            }
        }

        // Online softmax (row pair {r0, r0+8}); quad reduce via xor 1,2
#pragma unroll
        for (int r = 0; r < 2; r++) {
            const int i0 = 2 * r, i1 = 2 * r + 1;
            float rmax = -1e30f;
#pragma unroll
            for (int nf = 0; nf < 8; nf++)
                rmax = fmaxf(rmax, fmaxf(s[nf][i0], s[nf][i1]));
            rmax = fmaxf(rmax, __shfl_xor_sync(0xffffffffu, rmax, 1));
            rmax = fmaxf(rmax, __shfl_xor_sync(0xffffffffu, rmax, 2));
            float mnew = fmaxf(mi[r], rmax);
            float corr = __expf(mi[r] - mnew);
            float psum = 0.0f;
#pragma unroll
            for (int nf = 0; nf < 8; nf++) {
                float p0 = __expf(s[nf][i0] - mnew);
                float p1 = __expf(s[nf][i1] - mnew);
                s[nf][i0] = p0; s[nf][i1] = p1;
                psum += p0 + p1;
            }
            psum += __shfl_xor_sync(0xffffffffu, psum, 1);
            psum += __shfl_xor_sync(0xffffffffu, psum, 2);
            li[r] = li[r] * corr + psum;
            mi[r] = mnew;
#pragma unroll
            for (int nf = 0; nf < 16; nf++) { o[nf][i0] *= corr; o[nf][i1] *= corr; }
        }

        // P -> per-warp smem as fp16 (C-frag -> A-frag re-layout)
#pragma unroll
        for (int nf = 0; nf < 8; nf++) {
            *(__half2*)(Ps + (w * 16 + g) * APSTR + nf * 8 + 2 * c)     = h2(s[nf][0], s[nf][1]);
            *(__half2*)(Ps + (w * 16 + g + 8) * APSTR + nf * 8 + 2 * c) = h2(s[nf][2], s[nf][3]);
        }
        __syncwarp();

        // O += P @ V   (B frags via ldmatrix.trans on swizzled V tile)
#pragma unroll
        for (int kst = 0; kst < 4; kst++) {
            unsigned pa[4];
            const __half* pp = Ps + (w * 16 + ((lane >> 3) & 1) * 8 + (lane & 7)) * APSTR
                                  + kst * 16 + (lane >> 4) * 8;
            ldsm4(pa, pp);
#pragma unroll
            for (int nfp = 0; nfp < 8; nfp++) {
                unsigned vb[4];
                int rV = kst * 16 + ((lane >> 3) & 1) * 8 + (lane & 7);
                int cV = nfp * 2 + (lane >> 4);
                ldsm4t(vb, Vs + AIDX(rV, cV));
                mma16(o[nfp * 2],     pa, vb[0], vb[1]);
                mma16(o[nfp * 2 + 1], pa, vb[2], vb[3]);
            }
        }
        __syncthreads();
    }

    // Epilogue: normalize, write fp16 AO in [B,T,D]
    const float inv0 = 1.0f / li[0], inv1 = 1.0f / li[1];
    __half* dst0 = g_AOh + ((size_t)(b * TT + r0) * DD) + h * DKK;
    __half* dst1 = dst0 + (size_t)8 * DD;
#pragma unroll
    for (int nf = 0; nf < 16; nf++) {
        int col = nf * 8 + 2 * c;
        *(__half2*)(dst0 + col) = h2(o[nf][0] * inv0, o[nf][1] * inv0);
        *(__half2*)(dst1 + col) = h2(o[nf][2] * inv1, o[nf][3] * inv1);
    }
}

// ---------------------------------------------------------------------------
// Launcher. Inputs: 0 query, 1 key, 2 value, 3 mask(all-false, unused),
// 4 rel_bias, 5 Wq, 6 Wk, 7 Wv, 8 Wo, 9 bo, 10 is_causal
// ---------------------------------------------------------------------------
extern "C" void kernel_launch(void* const* d_in, const int* in_sizes, int n_in,
                              void* d_out, int out_size)
{
    (void)in_sizes; (void)n_in; (void)out_size;
    const float* query    = (const float*)d_in[0];
    const float* key      = (const float*)d_in[1];
    const float* value    = (const float*)d_in[2];
    const float* rel_bias = (const float*)d_in[4];
    const float* Wq       = (const float*)d_in[5];
    const float* Wk       = (const float*)d_in[6];
    const float* Wv       = (const float*)d_in[7];
    const float* Wo       = (const float*)d_in[8];
    const float* bo       = (const float*)d_in[9];
    const int* is_causal  = (const int*)d_in[10];
    float* out            = (float*)d_out;

    // 1) QKV projections (fp16 mma, z-fused)
    gemm_qkv_kernel<<<dim3(MM / 128, DD / 128, 3), 256>>>(query, key, value, Wq, Wk, Wv);

    // 2) Bias transpose -> fp16
    bias_transpose_kernel<<<dim3(TT / 256, TT, BB), 256>>>(rel_bias);

    // 3) Flash attention (fp16 mma + ldmatrix, swizzled K/V)
    const int attn_smem = (2 * 64 * 128 + 128 * APSTR) * (int)sizeof(__half); // 51200 B
    cudaFuncSetAttribute(attn_h_kernel, cudaFuncAttributeMaxDynamicSharedMemorySize, attn_smem);
    attn_h_kernel<<<dim3(TT / 128, HH, BB), 256, attn_smem>>>(is_causal);

    // 4) Output projection + bias (fp16 mma, fp32 out)
    gemm_out_kernel<<<dim3(MM / 128, DD / 128), 256>>>(Wo, bo, out);
}

// round 9
// speedup vs baseline: 6.8684x; 1.5996x over previous
#include <cuda_runtime.h>
#include <cuda_fp16.h>
#include <cstdint>

// Problem constants
#define BB   2
#define TT   2048
#define DD   1024
#define HH   8
#define DKK  128
#define MM   (BB*TT)

// ---------------------------------------------------------------------------
// Scratch (device globals — no allocations allowed). All intermediates fp16.
// ---------------------------------------------------------------------------
__device__ __half g_Qh[(size_t)BB*HH*TT*DKK];      // [B,H,T,DK] (pre-scaled by 1/sqrt(dk))
__device__ __half g_Kh[(size_t)BB*HH*TT*DKK];
__device__ __half g_Vh[(size_t)BB*HH*TT*DKK];
__device__ __half g_AOh[(size_t)BB*TT*DD];         // [B,T,D]
__device__ __half g_biasTh[(size_t)BB*HH*TT*TT];   // [B,H,Tq,Tk] 128 MB

// fp16 copies of GEMM operands (pre-converted once)
__device__ __half g_Xqh[(size_t)MM*DD];            // query fp16
__device__ __half g_Xkh[(size_t)MM*DD];            // key fp16
__device__ __half g_Xvh[(size_t)MM*DD];            // value fp16
__device__ __half g_Wqh[(size_t)DD*DD];
__device__ __half g_Wkh[(size_t)DD*DD];
__device__ __half g_Wvh[(size_t)DD*DD];
__device__ __half g_Woh[(size_t)DD*DD];

// ---------------------------------------------------------------------------
// Helpers
// ---------------------------------------------------------------------------
__device__ __forceinline__ __half2 h2(float x, float y) { return __floats2half2_rn(x, y); }
__device__ __forceinline__ unsigned packh2(float x, float y) {
    __half2 v = __floats2half2_rn(x, y);
    return *(unsigned*)&v;
}
__device__ __forceinline__ uint4 pack8(float4 a, float4 b) {
    uint4 u;
    u.x = packh2(a.x, a.y); u.y = packh2(a.z, a.w);
    u.z = packh2(b.x, b.y); u.w = packh2(b.z, b.w);
    return u;
}
__device__ __forceinline__ void ldsm4(unsigned r[4], const __half* p) {
    unsigned a = (unsigned)__cvta_generic_to_shared((void*)p);
    asm volatile("ldmatrix.sync.aligned.m8n8.x4.shared.b16 {%0,%1,%2,%3}, [%4];"
                 : "=r"(r[0]), "=r"(r[1]), "=r"(r[2]), "=r"(r[3]) : "r"(a));
}
__device__ __forceinline__ void ldsm4t(unsigned r[4], const __half* p) {
    unsigned a = (unsigned)__cvta_generic_to_shared((void*)p);
    asm volatile("ldmatrix.sync.aligned.m8n8.x4.trans.shared.b16 {%0,%1,%2,%3}, [%4];"
                 : "=r"(r[0]), "=r"(r[1]), "=r"(r[2]), "=r"(r[3]) : "r"(a));
}
__device__ __forceinline__ void mma16(float c[4], const unsigned a[4],
                                      unsigned b0, unsigned b1) {
    asm volatile(
        "mma.sync.aligned.m16n8k16.row.col.f32.f16.f16.f32 "
        "{%0,%1,%2,%3},{%4,%5,%6,%7},{%8,%9},{%0,%1,%2,%3};"
        : "+f"(c[0]), "+f"(c[1]), "+f"(c[2]), "+f"(c[3])
        : "r"(a[0]), "r"(a[1]), "r"(a[2]), "r"(a[3]), "r"(b0), "r"(b1));
}
__device__ __forceinline__ void cpa16(const __half* smem_dst, const __half* gsrc) {
    unsigned d = (unsigned)__cvta_generic_to_shared((void*)smem_dst);
    asm volatile("cp.async.cg.shared.global [%0], [%1], 16;" :: "r"(d), "l"(gsrc));
}
__device__ __forceinline__ void cpa_commit() {
    asm volatile("cp.async.commit_group;" ::: "memory");
}
template<int N> __device__ __forceinline__ void cpa_wait() {
    asm volatile("cp.async.wait_group %0;" :: "n"(N) : "memory");
}

// SW128-style swizzle over 128-byte rows (byte offset within a tile)
#define SWZ(off) ((off) ^ (((off) >> 3) & 0x70))

// ---------------------------------------------------------------------------
// Pre-convert fp32 -> fp16 (7 arrays, blockIdx.y selects)
// ---------------------------------------------------------------------------
__global__ void __launch_bounds__(256) f2h_kernel(
    const float* __restrict__ q, const float* __restrict__ k, const float* __restrict__ v,
    const float* __restrict__ wq, const float* __restrict__ wk,
    const float* __restrict__ wv, const float* __restrict__ wo)
{
    const int y = blockIdx.y;
    const float* src; __half* dst; size_t n;
    switch (y) {
        case 0: src = q;  dst = g_Xqh; n = (size_t)MM * DD; break;
        case 1: src = k;  dst = g_Xkh; n = (size_t)MM * DD; break;
        case 2: src = v;  dst = g_Xvh; n = (size_t)MM * DD; break;
        case 3: src = wq; dst = g_Wqh; n = (size_t)DD * DD; break;
        case 4: src = wk; dst = g_Wkh; n = (size_t)DD * DD; break;
        case 5: src = wv; dst = g_Wvh; n = (size_t)DD * DD; break;
        default: src = wo; dst = g_Woh; n = (size_t)DD * DD; break;
    }
    size_t i = ((size_t)blockIdx.x * 256 + threadIdx.x) * 8;
    if (i >= n) return;
    float4 a = *(const float4*)(src + i);
    float4 b = *(const float4*)(src + i + 4);
    *(uint4*)(dst + i) = pack8(a, b);
}

// ---------------------------------------------------------------------------
// fp16 GEMM, cp.async 3-stage pipeline: D[m,n] = sum_k X[m,k]*W[n,k]
// CTA 128x128, BK=64 halves (128B rows, SWZ), 8 warps (2m x 4n), warp 64x32.
// ---------------------------------------------------------------------------
#define NST    3
#define TILEB  16384                    // 128 rows * 128 bytes
#define STAGEB (2 * TILEB)              // A + B
#define NKT    (DD / 64)                // 16

__device__ __forceinline__ void gemm_issue_stage(
    char* sm, int buf, const __half* X, const __half* W, int kt, int tid)
{
    char* A = sm + buf * STAGEB;
    char* B = A + TILEB;
#pragma unroll
    for (int j = 0; j < 4; j++) {
        int u = tid + j * 256;          // 0..1023
        int row = u >> 3, ch = u & 7;
        int off = SWZ(row * 128 + ch * 16);
        const __half* xs = X + (size_t)row * DD + kt * 64 + ch * 8;
        const __half* ws = W + (size_t)row * DD + kt * 64 + ch * 8;
        cpa16((__half*)(A + off), xs);
        cpa16((__half*)(B + off), ws);
    }
    cpa_commit();
}

__device__ __forceinline__ void gemm_pipeline(
    const __half* Xb, const __half* Wb, int m0, int n0,
    char* sm, float acc[4][4][4])
{
    const int tid = threadIdx.x;
    const int lane = tid & 31, wid = tid >> 5;
    const int wm = (wid & 1) * 64, wn = (wid >> 1) * 32;

#pragma unroll
    for (int mf = 0; mf < 4; mf++)
#pragma unroll
        for (int nf = 0; nf < 4; nf++)
#pragma unroll
            for (int r = 0; r < 4; r++) acc[mf][nf][r] = 0.0f;

    const __half* X = Xb + (size_t)m0 * DD;
    const __half* W = Wb + (size_t)n0 * DD;

    // prologue: 2 stages in flight
    gemm_issue_stage(sm, 0, X, W, 0, tid);
    gemm_issue_stage(sm, 1, X, W, 1, tid);

    const int rA = wm + ((lane >> 3) & 1) * 8 + (lane & 7);
    const int rB = wn + (lane >> 4) * 8 + (lane & 7);
    const int cAbase = (lane >> 4);         // + 2*ks
    const int cBbase = ((lane >> 3) & 1);   // + 2*ks

    for (int kt = 0; kt < NKT; kt++) {
        cpa_wait<NST - 2>();
        __syncthreads();
        if (kt + NST - 1 < NKT)
            gemm_issue_stage(sm, (kt + NST - 1) % NST, X, W, kt + NST - 1, tid);

        char* A = sm + (kt % NST) * STAGEB;
        char* B = A + TILEB;

#pragma unroll
        for (int ks = 0; ks < 4; ks++) {
            unsigned af[4][4];
#pragma unroll
            for (int mf = 0; mf < 4; mf++) {
                int off = SWZ((rA + mf * 16) * 128 + (2 * ks + cAbase) * 16);
                ldsm4(af[mf], (const __half*)(A + off));
            }
#pragma unroll
            for (int nfp = 0; nfp < 2; nfp++) {
                unsigned bf[4];
                int off = SWZ((rB + nfp * 16) * 128 + (2 * ks + cBbase) * 16);
                ldsm4(bf, (const __half*)(B + off));
#pragma unroll
                for (int mf = 0; mf < 4; mf++) {
                    mma16(acc[mf][nfp * 2],     af[mf], bf[0], bf[1]);
                    mma16(acc[mf][nfp * 2 + 1], af[mf], bf[2], bf[3]);
                }
            }
        }
        __syncthreads();
    }
}

// QKV projection: z picks (input, weight, output); fp16 scatter to [B,H,T,DK].
__global__ void __launch_bounds__(256) gemm_qkv_kernel()
{
    extern __shared__ char sm[];
    const int z = blockIdx.z;
    const __half* X = (z == 0) ? g_Xqh : (z == 1) ? g_Xkh : g_Xvh;
    const __half* W = (z == 0) ? g_Wqh : (z == 1) ? g_Wkh : g_Wvh;
    __half* outp   = (z == 0) ? g_Qh  : (z == 1) ? g_Kh  : g_Vh;
    const float sc = (z == 0) ? 0.08838834764831845f : 1.0f;

    const int m0 = blockIdx.x * 128, n0 = blockIdx.y * 128;
    float acc[4][4][4];
    gemm_pipeline(X, W, m0, n0, sm, acc);

    const int lane = threadIdx.x & 31, wid = threadIdx.x >> 5;
    const int wm = (wid & 1) * 64, wn = (wid >> 1) * 32;
    const int g = lane >> 2, c = lane & 3;

#pragma unroll
    for (int mf = 0; mf < 4; mf++) {
        int row = m0 + wm + mf * 16 + g;
#pragma unroll
        for (int nf = 0; nf < 4; nf++) {
            int col = n0 + wn + nf * 8 + 2 * c;
            int h = col >> 7, dk = col & 127;
            {
                int b = row >> 11, t = row & 2047;
                *(__half2*)(outp + ((size_t)(b * HH + h) * TT + t) * DKK + dk) =
                    h2(acc[mf][nf][0] * sc, acc[mf][nf][1] * sc);
            }
            {
                int row2 = row + 8;
                int b = row2 >> 11, t = row2 & 2047;
                *(__half2*)(outp + ((size_t)(b * HH + h) * TT + t) * DKK + dk) =
                    h2(acc[mf][nf][2] * sc, acc[mf][nf][3] * sc);
            }
        }
    }
}

// Output projection: out = AO @ Wo^T + bo  (fp32 output)
__global__ void __launch_bounds__(256) gemm_out_kernel(
    const float* __restrict__ bo, float* __restrict__ out)
{
    extern __shared__ char sm[];
    const int m0 = blockIdx.x * 128, n0 = blockIdx.y * 128;
    float acc[4][4][4];
    gemm_pipeline(g_AOh, g_Woh, m0, n0, sm, acc);

    const int lane = threadIdx.x & 31, wid = threadIdx.x >> 5;
    const int wm = (wid & 1) * 64, wn = (wid >> 1) * 32;
    const int g = lane >> 2, c = lane & 3;

#pragma unroll
    for (int mf = 0; mf < 4; mf++) {
        int row = m0 + wm + mf * 16 + g;
#pragma unroll
        for (int nf = 0; nf < 4; nf++) {
            int col = n0 + wn + nf * 8 + 2 * c;
            float2 bias = *(const float2*)(bo + col);
            *(float2*)(out + (size_t)row * DD + col) =
                make_float2(acc[mf][nf][0] + bias.x, acc[mf][nf][1] + bias.y);
            *(float2*)(out + (size_t)(row + 8) * DD + col) =
                make_float2(acc[mf][nf][2] + bias.x, acc[mf][nf][3] + bias.y);
        }
    }
}

// ---------------------------------------------------------------------------
// rel_bias transpose [B,Tq,Tk,H] fp32 -> [B,H,Tq,Tk] fp16  (unchanged)
// ---------------------------------------------------------------------------
__global__ void __launch_bounds__(256) bias_transpose_kernel(const float* __restrict__ rb)
{
    __shared__ __half smt[8][264];
    const int b = blockIdx.z, q = blockIdx.y, kc = blockIdx.x * 256;
    const int k = threadIdx.x;

    const float* src = rb + ((size_t)(b * TT + q) * TT + kc + k) * HH;
    float4 v0 = *(const float4*)(src);
    float4 v1 = *(const float4*)(src + 4);
    smt[0][k] = __float2half(v0.x); smt[1][k] = __float2half(v0.y);
    smt[2][k] = __float2half(v0.z); smt[3][k] = __float2half(v0.w);
    smt[4][k] = __float2half(v1.x); smt[5][k] = __float2half(v1.y);
    smt[6][k] = __float2half(v1.z); smt[7][k] = __float2half(v1.w);
    __syncthreads();
#pragma unroll
    for (int h = 0; h < HH; h++)
        g_biasTh[((size_t)(b * HH + h) * TT + q) * TT + kc + k] = smt[h][k];
}

// ---------------------------------------------------------------------------
// Flash attention (unchanged from round-6 passing kernel)
// ---------------------------------------------------------------------------
#define SATT(r) (((((r) & 1) << 2) | ((r) & 2) | (((r) >> 2) & 1)))
#define AIDX(r, c) (((r) << 7) + ((((c) ^ SATT((r) & 7))) << 3))
#define APSTR 72

__global__ void __launch_bounds__(256) attn_h_kernel(const int* __restrict__ is_causal_p)
{
    extern __shared__ __half smh[];
    __half* Ks = smh;
    __half* Vs = Ks + 64 * 128;
    __half* Ps = Vs + 64 * 128;

    const int q0 = ((int)gridDim.x - 1 - (int)blockIdx.x) * 128;
    const int h = blockIdx.y, b = blockIdx.z;
    const int tid = threadIdx.x, lane = tid & 31, w = tid >> 5;
    const int g = lane >> 2, c = lane & 3;
    const bool causal = (is_causal_p[0] != 0);

    const __half* Qg = g_Qh + (size_t)(b * HH + h) * TT * DKK;
    const __half* Kg = g_Kh + (size_t)(b * HH + h) * TT * DKK;
    const __half* Vg = g_Vh + (size_t)(b * HH + h) * TT * DKK;
    const __half* Bg = g_biasTh + (size_t)(b * HH + h) * TT * TT;

    const int r0 = q0 + w * 16 + g;

    unsigned qa[8][4];
#pragma unroll
    for (int ks = 0; ks < 8; ks++) {
        const __half* p = Qg + (size_t)r0 * DKK + ks * 16 + 2 * c;
        qa[ks][0] = *(const unsigned*)(p);
        qa[ks][1] = *(const unsigned*)(p + 8 * DKK);
        qa[ks][2] = *(const unsigned*)(p + 8);
        qa[ks][3] = *(const unsigned*)(p + 8 * DKK + 8);
    }

    float o[16][4];
#pragma unroll
    for (int nf = 0; nf < 16; nf++)
#pragma unroll
        for (int r = 0; r < 4; r++) o[nf][r] = 0.0f;
    float mi[2] = {-1e30f, -1e30f}, li[2] = {0.0f, 0.0f};

    const int ntiles = causal ? (q0 / 64 + 2) : (TT / 64);
    const int srow = tid >> 2;
    const int scb  = tid & 3;

    for (int kt = 0; kt < ntiles; kt++) {
        const int k0 = kt * 64;
        {
            const __half* kg = Kg + (size_t)(k0 + srow) * DKK + scb * 8;
            const __half* vg = Vg + (size_t)(k0 + srow) * DKK + scb * 8;
#pragma unroll
            for (int j = 0; j < 4; j++) {
                int ch = scb + 4 * j;
                *(uint4*)(Ks + AIDX(srow, ch)) = *(const uint4*)(kg + 32 * j);
                *(uint4*)(Vs + AIDX(srow, ch)) = *(const uint4*)(vg + 32 * j);
            }
        }
        __syncthreads();

        float s[8][4];
#pragma unroll
        for (int nf = 0; nf < 8; nf++) {
            const __half* bp = Bg + (size_t)r0 * TT + k0 + nf * 8 + 2 * c;
            float2 b01 = __half22float2(*(const __half2*)bp);
            float2 b23 = __half22float2(*(const __half2*)(bp + (size_t)8 * TT));
            s[nf][0] = b01.x; s[nf][1] = b01.y; s[nf][2] = b23.x; s[nf][3] = b23.y;
        }

#pragma unroll
        for (int ks = 0; ks < 8; ks++) {
#pragma unroll
            for (int nfp = 0; nfp < 4; nfp++) {
                unsigned bf[4];
                int rB = nfp * 16 + (lane >> 4) * 8 + (lane & 7);
                int cB = 2 * ks + ((lane >> 3) & 1);
                ldsm4(bf, Ks + AIDX(rB, cB));
                mma16(s[nfp * 2],     qa[ks], bf[0], bf[1]);
                mma16(s[nfp * 2 + 1], qa[ks], bf[2], bf[3]);
            }
        }

        if (causal && k0 + 63 > q0 + w * 16) {
#pragma unroll
            for (int nf = 0; nf < 8; nf++) {
                int col = k0 + nf * 8 + 2 * c;
                if (col     > r0)     s[nf][0] = -1e30f;
                if (col + 1 > r0)     s[nf][1] = -1e30f;
                if (col     > r0 + 8) s[nf][2] = -1e30f;
                if (col + 1 > r0 + 8) s[nf][3] = -1e30f;
            }
        }

#pragma unroll
        for (int r = 0; r < 2; r++) {
            const int i0 = 2 * r, i1 = 2 * r + 1;
            float rmax = -1e30f;
#pragma unroll
            for (int nf = 0; nf < 8; nf++)
                rmax = fmaxf(rmax, fmaxf(s[nf][i0], s[nf][i1]));
            rmax = fmaxf(rmax, __shfl_xor_sync(0xffffffffu, rmax, 1));
            rmax = fmaxf(rmax, __shfl_xor_sync(0xffffffffu, rmax, 2));
            float mnew = fmaxf(mi[r], rmax);
            float corr = __expf(mi[r] - mnew);
            float psum = 0.0f;
#pragma unroll
            for (int nf = 0; nf < 8; nf++) {
                float p0 = __expf(s[nf][i0] - mnew);
                float p1 = __expf(s[nf][i1] - mnew);
                s[nf][i0] = p0; s[nf][i1] = p1;
                psum += p0 + p1;
            }
            psum += __shfl_xor_sync(0xffffffffu, psum, 1);
            psum += __shfl_xor_sync(0xffffffffu, psum, 2);
            li[r] = li[r] * corr + psum;
            mi[r] = mnew;
#pragma unroll
            for (int nf = 0; nf < 16; nf++) { o[nf][i0] *= corr; o[nf][i1] *= corr; }
        }

#pragma unroll
        for (int nf = 0; nf < 8; nf++) {
            *(__half2*)(Ps + (w * 16 + g) * APSTR + nf * 8 + 2 * c)     = h2(s[nf][0], s[nf][1]);
            *(__half2*)(Ps + (w * 16 + g + 8) * APSTR + nf * 8 + 2 * c) = h2(s[nf][2], s[nf][3]);
        }
        __syncwarp();

#pragma unroll
        for (int kst = 0; kst < 4; kst++) {
            unsigned pa[4];
            const __half* pp = Ps + (w * 16 + ((lane >> 3) & 1) * 8 + (lane & 7)) * APSTR
                                  + kst * 16 + (lane >> 4) * 8;
            ldsm4(pa, pp);
#pragma unroll
            for (int nfp = 0; nfp < 8; nfp++) {
                unsigned vb[4];
                int rV = kst * 16 + ((lane >> 3) & 1) * 8 + (lane & 7);
                int cV = nfp * 2 + (lane >> 4);
                ldsm4t(vb, Vs + AIDX(rV, cV));
                mma16(o[nfp * 2],     pa, vb[0], vb[1]);
                mma16(o[nfp * 2 + 1], pa, vb[2], vb[3]);
            }
        }
        __syncthreads();
    }

    const float inv0 = 1.0f / li[0], inv1 = 1.0f / li[1];
    __half* dst0 = g_AOh + ((size_t)(b * TT + r0) * DD) + h * DKK;
    __half* dst1 = dst0 + (size_t)8 * DD;
#pragma unroll
    for (int nf = 0; nf < 16; nf++) {
        int col = nf * 8 + 2 * c;
        *(__half2*)(dst0 + col) = h2(o[nf][0] * inv0, o[nf][1] * inv0);
        *(__half2*)(dst1 + col) = h2(o[nf][2] * inv1, o[nf][3] * inv1);
    }
}

// ---------------------------------------------------------------------------
// Launcher. Inputs: 0 query, 1 key, 2 value, 3 mask(all-false, unused),
// 4 rel_bias, 5 Wq, 6 Wk, 7 Wv, 8 Wo, 9 bo, 10 is_causal
// ---------------------------------------------------------------------------
extern "C" void kernel_launch(void* const* d_in, const int* in_sizes, int n_in,
                              void* d_out, int out_size)
{
    (void)in_sizes; (void)n_in; (void)out_size;
    const float* query    = (const float*)d_in[0];
    const float* key      = (const float*)d_in[1];
    const float* value    = (const float*)d_in[2];
    const float* rel_bias = (const float*)d_in[4];
    const float* Wq       = (const float*)d_in[5];
    const float* Wk       = (const float*)d_in[6];
    const float* Wv       = (const float*)d_in[7];
    const float* Wo       = (const float*)d_in[8];
    const float* bo       = (const float*)d_in[9];
    const int* is_causal  = (const int*)d_in[10];
    float* out            = (float*)d_out;

    const int gemm_smem = NST * STAGEB;   // 98304 B
    cudaFuncSetAttribute(gemm_qkv_kernel, cudaFuncAttributeMaxDynamicSharedMemorySize, gemm_smem);
    cudaFuncSetAttribute(gemm_out_kernel, cudaFuncAttributeMaxDynamicSharedMemorySize, gemm_smem);

    // 0) Pre-convert all GEMM operands to fp16 (X: 4M elems -> 2048 blocks @8/thread)
    f2h_kernel<<<dim3(2048, 7), 256>>>(query, key, value, Wq, Wk, Wv, Wo);

    // 1) QKV projections (fp16 mma, cp.async pipeline, z-fused)
    gemm_qkv_kernel<<<dim3(MM / 128, DD / 128, 3), 256, gemm_smem>>>();

    // 2) Bias transpose -> fp16
    bias_transpose_kernel<<<dim3(TT / 256, TT, BB), 256>>>(rel_bias);

    // 3) Flash attention (fp16 mma + ldmatrix)
    const int attn_smem = (2 * 64 * 128 + 128 * APSTR) * (int)sizeof(__half); // 51200 B
    cudaFuncSetAttribute(attn_h_kernel, cudaFuncAttributeMaxDynamicSharedMemorySize, attn_smem);
    attn_h_kernel<<<dim3(TT / 128, HH, BB), 256, attn_smem>>>(is_causal);

    // 4) Output projection + bias (fp16 mma, cp.async pipeline)
    gemm_out_kernel<<<dim3(MM / 128, DD / 128), 256, gemm_smem>>>(bo, out);
}

// round 10
// speedup vs baseline: 8.0915x; 1.1781x over previous
#include <cuda_runtime.h>
#include <cuda_fp16.h>
#include <cstdint>

// Problem constants
#define BB   2
#define TT   2048
#define DD   1024
#define HH   8
#define DKK  128
#define MM   (BB*TT)

// ---------------------------------------------------------------------------
// Scratch (device globals — no allocations allowed). All intermediates fp16.
// ---------------------------------------------------------------------------
__device__ __half g_Qh[(size_t)BB*HH*TT*DKK];      // [B,H,T,DK] (pre-scaled by 1/sqrt(dk))
__device__ __half g_Kh[(size_t)BB*HH*TT*DKK];
__device__ __half g_Vh[(size_t)BB*HH*TT*DKK];
__device__ __half g_AOh[(size_t)BB*TT*DD];         // [B,T,D]
__device__ __half g_biasTh[(size_t)BB*HH*TT*TT];   // [B,H,Tq,Tk] 128 MB

// fp16 copies of GEMM operands (pre-converted once)
__device__ __half g_Xqh[(size_t)MM*DD];
__device__ __half g_Xkh[(size_t)MM*DD];
__device__ __half g_Xvh[(size_t)MM*DD];
__device__ __half g_Wqh[(size_t)DD*DD];
__device__ __half g_Wkh[(size_t)DD*DD];
__device__ __half g_Wvh[(size_t)DD*DD];
__device__ __half g_Woh[(size_t)DD*DD];

// ---------------------------------------------------------------------------
// Helpers
// ---------------------------------------------------------------------------
__device__ __forceinline__ __half2 h2(float x, float y) { return __floats2half2_rn(x, y); }
__device__ __forceinline__ unsigned packh2(float x, float y) {
    __half2 v = __floats2half2_rn(x, y);
    return *(unsigned*)&v;
}
__device__ __forceinline__ uint4 pack8(float4 a, float4 b) {
    uint4 u;
    u.x = packh2(a.x, a.y); u.y = packh2(a.z, a.w);
    u.z = packh2(b.x, b.y); u.w = packh2(b.z, b.w);
    return u;
}
__device__ __forceinline__ void ldsm4(unsigned r[4], const __half* p) {
    unsigned a = (unsigned)__cvta_generic_to_shared((void*)p);
    asm volatile("ldmatrix.sync.aligned.m8n8.x4.shared.b16 {%0,%1,%2,%3}, [%4];"
                 : "=r"(r[0]), "=r"(r[1]), "=r"(r[2]), "=r"(r[3]) : "r"(a));
}
__device__ __forceinline__ void ldsm4t(unsigned r[4], const __half* p) {
    unsigned a = (unsigned)__cvta_generic_to_shared((void*)p);
    asm volatile("ldmatrix.sync.aligned.m8n8.x4.trans.shared.b16 {%0,%1,%2,%3}, [%4];"
                 : "=r"(r[0]), "=r"(r[1]), "=r"(r[2]), "=r"(r[3]) : "r"(a));
}
__device__ __forceinline__ void mma16(float c[4], const unsigned a[4],
                                      unsigned b0, unsigned b1) {
    asm volatile(
        "mma.sync.aligned.m16n8k16.row.col.f32.f16.f16.f32 "
        "{%0,%1,%2,%3},{%4,%5,%6,%7},{%8,%9},{%0,%1,%2,%3};"
        : "+f"(c[0]), "+f"(c[1]), "+f"(c[2]), "+f"(c[3])
        : "r"(a[0]), "r"(a[1]), "r"(a[2]), "r"(a[3]), "r"(b0), "r"(b1));
}
__device__ __forceinline__ void cpa16(const __half* smem_dst, const __half* gsrc) {
    unsigned d = (unsigned)__cvta_generic_to_shared((void*)smem_dst);
    asm volatile("cp.async.cg.shared.global [%0], [%1], 16;" :: "r"(d), "l"(gsrc));
}
__device__ __forceinline__ void cpa_commit() {
    asm volatile("cp.async.commit_group;" ::: "memory");
}
template<int N> __device__ __forceinline__ void cpa_wait() {
    asm volatile("cp.async.wait_group %0;" :: "n"(N) : "memory");
}

// SW128-style swizzle over 128-byte rows (byte offset within a tile)
#define SWZ(off) ((off) ^ (((off) >> 3) & 0x70))

// ---------------------------------------------------------------------------
// Pre-convert fp32 -> fp16 (7 arrays, blockIdx.y selects)
// ---------------------------------------------------------------------------
__global__ void __launch_bounds__(256) f2h_kernel(
    const float* __restrict__ q, const float* __restrict__ k, const float* __restrict__ v,
    const float* __restrict__ wq, const float* __restrict__ wk,
    const float* __restrict__ wv, const float* __restrict__ wo)
{
    const int y = blockIdx.y;
    const float* src; __half* dst; size_t n;
    switch (y) {
        case 0: src = q;  dst = g_Xqh; n = (size_t)MM * DD; break;
        case 1: src = k;  dst = g_Xkh; n = (size_t)MM * DD; break;
        case 2: src = v;  dst = g_Xvh; n = (size_t)MM * DD; break;
        case 3: src = wq; dst = g_Wqh; n = (size_t)DD * DD; break;
        case 4: src = wk; dst = g_Wkh; n = (size_t)DD * DD; break;
        case 5: src = wv; dst = g_Wvh; n = (size_t)DD * DD; break;
        default: src = wo; dst = g_Woh; n = (size_t)DD * DD; break;
    }
    size_t i = ((size_t)blockIdx.x * 256 + threadIdx.x) * 8;
    if (i >= n) return;
    float4 a = *(const float4*)(src + i);
    float4 b = *(const float4*)(src + i + 4);
    *(uint4*)(dst + i) = pack8(a, b);
}

// ---------------------------------------------------------------------------
// fp16 GEMM, cp.async 3-stage pipeline (unchanged from round 8)
// ---------------------------------------------------------------------------
#define NST    3
#define TILEB  16384
#define STAGEB (2 * TILEB)
#define NKT    (DD / 64)

__device__ __forceinline__ void gemm_issue_stage(
    char* sm, int buf, const __half* X, const __half* W, int kt, int tid)
{
    char* A = sm + buf * STAGEB;
    char* B = A + TILEB;
#pragma unroll
    for (int j = 0; j < 4; j++) {
        int u = tid + j * 256;
        int row = u >> 3, ch = u & 7;
        int off = SWZ(row * 128 + ch * 16);
        const __half* xs = X + (size_t)row * DD + kt * 64 + ch * 8;
        const __half* ws = W + (size_t)row * DD + kt * 64 + ch * 8;
        cpa16((__half*)(A + off), xs);
        cpa16((__half*)(B + off), ws);
    }
    cpa_commit();
}

__device__ __forceinline__ void gemm_pipeline(
    const __half* Xb, const __half* Wb, int m0, int n0,
    char* sm, float acc[4][4][4])
{
    const int tid = threadIdx.x;
    const int lane = tid & 31, wid = tid >> 5;
    const int wm = (wid & 1) * 64, wn = (wid >> 1) * 32;

#pragma unroll
    for (int mf = 0; mf < 4; mf++)
#pragma unroll
        for (int nf = 0; nf < 4; nf++)
#pragma unroll
            for (int r = 0; r < 4; r++) acc[mf][nf][r] = 0.0f;

    const __half* X = Xb + (size_t)m0 * DD;
    const __half* W = Wb + (size_t)n0 * DD;

    gemm_issue_stage(sm, 0, X, W, 0, tid);
    gemm_issue_stage(sm, 1, X, W, 1, tid);

    const int rA = wm + ((lane >> 3) & 1) * 8 + (lane & 7);
    const int rB = wn + (lane >> 4) * 8 + (lane & 7);
    const int cAbase = (lane >> 4);
    const int cBbase = ((lane >> 3) & 1);

    for (int kt = 0; kt < NKT; kt++) {
        cpa_wait<NST - 2>();
        __syncthreads();
        if (kt + NST - 1 < NKT)
            gemm_issue_stage(sm, (kt + NST - 1) % NST, X, W, kt + NST - 1, tid);

        char* A = sm + (kt % NST) * STAGEB;
        char* B = A + TILEB;

#pragma unroll
        for (int ks = 0; ks < 4; ks++) {
            unsigned af[4][4];
#pragma unroll
            for (int mf = 0; mf < 4; mf++) {
                int off = SWZ((rA + mf * 16) * 128 + (2 * ks + cAbase) * 16);
                ldsm4(af[mf], (const __half*)(A + off));
            }
#pragma unroll
            for (int nfp = 0; nfp < 2; nfp++) {
                unsigned bf[4];
                int off = SWZ((rB + nfp * 16) * 128 + (2 * ks + cBbase) * 16);
                ldsm4(bf, (const __half*)(B + off));
#pragma unroll
                for (int mf = 0; mf < 4; mf++) {
                    mma16(acc[mf][nfp * 2],     af[mf], bf[0], bf[1]);
                    mma16(acc[mf][nfp * 2 + 1], af[mf], bf[2], bf[3]);
                }
            }
        }
        __syncthreads();
    }
}

__global__ void __launch_bounds__(256) gemm_qkv_kernel()
{
    extern __shared__ char sm[];
    const int z = blockIdx.z;
    const __half* X = (z == 0) ? g_Xqh : (z == 1) ? g_Xkh : g_Xvh;
    const __half* W = (z == 0) ? g_Wqh : (z == 1) ? g_Wkh : g_Wvh;
    __half* outp   = (z == 0) ? g_Qh  : (z == 1) ? g_Kh  : g_Vh;
    const float sc = (z == 0) ? 0.08838834764831845f : 1.0f;

    const int m0 = blockIdx.x * 128, n0 = blockIdx.y * 128;
    float acc[4][4][4];
    gemm_pipeline(X, W, m0, n0, sm, acc);

    const int lane = threadIdx.x & 31, wid = threadIdx.x >> 5;
    const int wm = (wid & 1) * 64, wn = (wid >> 1) * 32;
    const int g = lane >> 2, c = lane & 3;

#pragma unroll
    for (int mf = 0; mf < 4; mf++) {
        int row = m0 + wm + mf * 16 + g;
#pragma unroll
        for (int nf = 0; nf < 4; nf++) {
            int col = n0 + wn + nf * 8 + 2 * c;
            int h = col >> 7, dk = col & 127;
            {
                int b = row >> 11, t = row & 2047;
                *(__half2*)(outp + ((size_t)(b * HH + h) * TT + t) * DKK + dk) =
                    h2(acc[mf][nf][0] * sc, acc[mf][nf][1] * sc);
            }
            {
                int row2 = row + 8;
                int b = row2 >> 11, t = row2 & 2047;
                *(__half2*)(outp + ((size_t)(b * HH + h) * TT + t) * DKK + dk) =
                    h2(acc[mf][nf][2] * sc, acc[mf][nf][3] * sc);
            }
        }
    }
}

__global__ void __launch_bounds__(256) gemm_out_kernel(
    const float* __restrict__ bo, float* __restrict__ out)
{
    extern __shared__ char sm[];
    const int m0 = blockIdx.x * 128, n0 = blockIdx.y * 128;
    float acc[4][4][4];
    gemm_pipeline(g_AOh, g_Woh, m0, n0, sm, acc);

    const int lane = threadIdx.x & 31, wid = threadIdx.x >> 5;
    const int wm = (wid & 1) * 64, wn = (wid >> 1) * 32;
    const int g = lane >> 2, c = lane & 3;

#pragma unroll
    for (int mf = 0; mf < 4; mf++) {
        int row = m0 + wm + mf * 16 + g;
#pragma unroll
        for (int nf = 0; nf < 4; nf++) {
            int col = n0 + wn + nf * 8 + 2 * c;
            float2 bias = *(const float2*)(bo + col);
            *(float2*)(out + (size_t)row * DD + col) =
                make_float2(acc[mf][nf][0] + bias.x, acc[mf][nf][1] + bias.y);
            *(float2*)(out + (size_t)(row + 8) * DD + col) =
                make_float2(acc[mf][nf][2] + bias.x, acc[mf][nf][3] + bias.y);
        }
    }
}

// ---------------------------------------------------------------------------
// rel_bias transpose [B,Tq,Tk,H] fp32 -> [B,H,Tq,Tk] fp16  (unchanged)
// ---------------------------------------------------------------------------
__global__ void __launch_bounds__(256) bias_transpose_kernel(const float* __restrict__ rb)
{
    __shared__ __half smt[8][264];
    const int b = blockIdx.z, q = blockIdx.y, kc = blockIdx.x * 256;
    const int k = threadIdx.x;

    const float* src = rb + ((size_t)(b * TT + q) * TT + kc + k) * HH;
    float4 v0 = *(const float4*)(src);
    float4 v1 = *(const float4*)(src + 4);
    smt[0][k] = __float2half(v0.x); smt[1][k] = __float2half(v0.y);
    smt[2][k] = __float2half(v0.z); smt[3][k] = __float2half(v0.w);
    smt[4][k] = __float2half(v1.x); smt[5][k] = __float2half(v1.y);
    smt[6][k] = __float2half(v1.z); smt[7][k] = __float2half(v1.w);
    __syncthreads();
#pragma unroll
    for (int h = 0; h < HH; h++)
        g_biasTh[((size_t)(b * HH + h) * TT + q) * TT + kc + k] = smt[h][k];
}

// ---------------------------------------------------------------------------
// Flash attention: cp.async double-buffered K/V/bias pipeline.
// CTA = 128 q rows x (b,h), 8 warps, 16 q rows each.
// smem: K[2] 8192h, V[2] 8192h, Bias[2] 128x72h, P 128x72h  => 118 KB
// ---------------------------------------------------------------------------
#define SATT(r) (((((r) & 1) << 2) | ((r) & 2) | (((r) >> 2) & 1)))
#define AIDX(r, c) (((r) << 7) + ((((c) ^ SATT((r) & 7))) << 3))
#define APSTR 72
#define KVSZ  (64 * 128)              // halves per K or V tile
#define BSSZ  (128 * APSTR)           // halves per bias tile

__device__ __forceinline__ void attn_stage(
    __half* Ks, __half* Vs, __half* Bs,
    const __half* Kg, const __half* Vg, const __half* Bgt, int tid)
{
    const int srow = tid >> 2, scb = tid & 3;
    const __half* kg = Kg + (size_t)srow * DKK + scb * 8;
    const __half* vg = Vg + (size_t)srow * DKK + scb * 8;
#pragma unroll
    for (int j = 0; j < 4; j++) {
        int ch = scb + 4 * j;
        cpa16(Ks + AIDX(srow, ch), kg + 32 * j);
        cpa16(Vs + AIDX(srow, ch), vg + 32 * j);
    }
#pragma unroll
    for (int j = 0; j < 4; j++) {
        int u = tid + 256 * j;
        int row = u >> 3, ch = u & 7;
        cpa16(Bs + row * APSTR + ch * 8, Bgt + (size_t)row * TT + ch * 8);
    }
    cpa_commit();
}

__global__ void __launch_bounds__(256) attn_h_kernel(const int* __restrict__ is_causal_p)
{
    extern __shared__ __half smh[];
    __half* Kb[2] = { smh,             smh + KVSZ };
    __half* Vb[2] = { smh + 2 * KVSZ,  smh + 3 * KVSZ };
    __half* Bb[2] = { smh + 4 * KVSZ,  smh + 4 * KVSZ + BSSZ };
    __half* Ps    = smh + 4 * KVSZ + 2 * BSSZ;

    const int q0 = ((int)gridDim.x - 1 - (int)blockIdx.x) * 128;  // long CTAs first
    const int h = blockIdx.y, b = blockIdx.z;
    const int tid = threadIdx.x, lane = tid & 31, w = tid >> 5;
    const int g = lane >> 2, c = lane & 3;
    const bool causal = (is_causal_p[0] != 0);

    const __half* Qg = g_Qh + (size_t)(b * HH + h) * TT * DKK;
    const __half* Kg = g_Kh + (size_t)(b * HH + h) * TT * DKK;
    const __half* Vg = g_Vh + (size_t)(b * HH + h) * TT * DKK;
    const __half* Bg = g_biasTh + (size_t)(b * HH + h) * TT * TT + (size_t)q0 * TT;

    const int r0 = q0 + w * 16 + g;

    // Q A-fragments, register-resident (Q already scaled by 1/sqrt(dk))
    unsigned qa[8][4];
#pragma unroll
    for (int ks = 0; ks < 8; ks++) {
        const __half* p = Qg + (size_t)r0 * DKK + ks * 16 + 2 * c;
        qa[ks][0] = *(const unsigned*)(p);
        qa[ks][1] = *(const unsigned*)(p + 8 * DKK);
        qa[ks][2] = *(const unsigned*)(p + 8);
        qa[ks][3] = *(const unsigned*)(p + 8 * DKK + 8);
    }

    float o[16][4];
#pragma unroll
    for (int nf = 0; nf < 16; nf++)
#pragma unroll
        for (int r = 0; r < 4; r++) o[nf][r] = 0.0f;
    float mi[2] = {-1e30f, -1e30f}, li[2] = {0.0f, 0.0f};

    const int ntiles = causal ? (q0 / 64 + 2) : (TT / 64);

    // prologue: stage tile 0
    attn_stage(Kb[0], Vb[0], Bb[0], Kg, Vg, Bg, tid);

    for (int kt = 0; kt < ntiles; kt++) {
        const int k0 = kt * 64;
        const int buf = kt & 1;

        // issue next tile into the other buffer (safe: its last reader finished
        // at the trailing __syncthreads of iteration kt-1)
        if (kt + 1 < ntiles) {
            const int k1 = (kt + 1) * 64;
            attn_stage(Kb[buf ^ 1], Vb[buf ^ 1], Bb[buf ^ 1],
                       Kg + (size_t)k1 * DKK, Vg + (size_t)k1 * DKK, Bg + k1, tid);
            cpa_wait<1>();
        } else {
            cpa_wait<0>();
        }
        __syncthreads();

        __half* Ks = Kb[buf];
        __half* Vs = Vb[buf];
        const __half* Bs = Bb[buf];

        // S accum initialized with bias (from smem, conflict-free)
        float s[8][4];
#pragma unroll
        for (int nf = 0; nf < 8; nf++) {
            const __half* bp = Bs + (w * 16 + g) * APSTR + nf * 8 + 2 * c;
            float2 b01 = __half22float2(*(const __half2*)bp);
            float2 b23 = __half22float2(*(const __half2*)(bp + 8 * APSTR));
            s[nf][0] = b01.x; s[nf][1] = b01.y; s[nf][2] = b23.x; s[nf][3] = b23.y;
        }

        // S += Q K^T
#pragma unroll
        for (int ks = 0; ks < 8; ks++) {
#pragma unroll
            for (int nfp = 0; nfp < 4; nfp++) {
                unsigned bf[4];
                int rB = nfp * 16 + (lane >> 4) * 8 + (lane & 7);
                int cB = 2 * ks + ((lane >> 3) & 1);
                ldsm4(bf, Ks + AIDX(rB, cB));
                mma16(s[nfp * 2],     qa[ks], bf[0], bf[1]);
                mma16(s[nfp * 2 + 1], qa[ks], bf[2], bf[3]);
            }
        }

        // Causal mask (only diagonal-crossing tiles for this warp)
        if (causal && k0 + 63 > q0 + w * 16) {
#pragma unroll
            for (int nf = 0; nf < 8; nf++) {
                int col = k0 + nf * 8 + 2 * c;
                if (col     > r0)     s[nf][0] = -1e30f;
                if (col + 1 > r0)     s[nf][1] = -1e30f;
                if (col     > r0 + 8) s[nf][2] = -1e30f;
                if (col + 1 > r0 + 8) s[nf][3] = -1e30f;
            }
        }

        // Online softmax (row pair {r0, r0+8}); quad reduce via xor 1,2
#pragma unroll
        for (int r = 0; r < 2; r++) {
            const int i0 = 2 * r, i1 = 2 * r + 1;
            float rmax = -1e30f;
#pragma unroll
            for (int nf = 0; nf < 8; nf++)
                rmax = fmaxf(rmax, fmaxf(s[nf][i0], s[nf][i1]));
            rmax = fmaxf(rmax, __shfl_xor_sync(0xffffffffu, rmax, 1));
            rmax = fmaxf(rmax, __shfl_xor_sync(0xffffffffu, rmax, 2));
            float mnew = fmaxf(mi[r], rmax);
            float corr = __expf(mi[r] - mnew);
            float psum = 0.0f;
#pragma unroll
            for (int nf = 0; nf < 8; nf++) {
                float p0 = __expf(s[nf][i0] - mnew);
                float p1 = __expf(s[nf][i1] - mnew);
                s[nf][i0] = p0; s[nf][i1] = p1;
                psum += p0 + p1;
            }
            psum += __shfl_xor_sync(0xffffffffu, psum, 1);
            psum += __shfl_xor_sync(0xffffffffu, psum, 2);
            li[r] = li[r] * corr + psum;
            mi[r] = mnew;
#pragma unroll
            for (int nf = 0; nf < 16; nf++) { o[nf][i0] *= corr; o[nf][i1] *= corr; }
        }

        // P -> per-warp smem as fp16 (C-frag -> A-frag re-layout)
#pragma unroll
        for (int nf = 0; nf < 8; nf++) {
            *(__half2*)(Ps + (w * 16 + g) * APSTR + nf * 8 + 2 * c)     = h2(s[nf][0], s[nf][1]);
            *(__half2*)(Ps + (w * 16 + g + 8) * APSTR + nf * 8 + 2 * c) = h2(s[nf][2], s[nf][3]);
        }
        __syncwarp();

        // O += P @ V
#pragma unroll
        for (int kst = 0; kst < 4; kst++) {
            unsigned pa[4];
            const __half* pp = Ps + (w * 16 + ((lane >> 3) & 1) * 8 + (lane & 7)) * APSTR
                                  + kst * 16 + (lane >> 4) * 8;
            ldsm4(pa, pp);
#pragma unroll
            for (int nfp = 0; nfp < 8; nfp++) {
                unsigned vb[4];
                int rV = kst * 16 + ((lane >> 3) & 1) * 8 + (lane & 7);
                int cV = nfp * 2 + (lane >> 4);
                ldsm4t(vb, Vs + AIDX(rV, cV));
                mma16(o[nfp * 2],     pa, vb[0], vb[1]);
                mma16(o[nfp * 2 + 1], pa, vb[2], vb[3]);
            }
        }
        __syncthreads();
    }

    // Epilogue: normalize, write fp16 AO in [B,T,D]
    const float inv0 = 1.0f / li[0], inv1 = 1.0f / li[1];
    __half* dst0 = g_AOh + ((size_t)(b * TT + r0) * DD) + h * DKK;
    __half* dst1 = dst0 + (size_t)8 * DD;
#pragma unroll
    for (int nf = 0; nf < 16; nf++) {
        int col = nf * 8 + 2 * c;
        *(__half2*)(dst0 + col) = h2(o[nf][0] * inv0, o[nf][1] * inv0);
        *(__half2*)(dst1 + col) = h2(o[nf][2] * inv1, o[nf][3] * inv1);
    }
}

// ---------------------------------------------------------------------------
// Launcher. Inputs: 0 query, 1 key, 2 value, 3 mask(all-false, unused),
// 4 rel_bias, 5 Wq, 6 Wk, 7 Wv, 8 Wo, 9 bo, 10 is_causal
// ---------------------------------------------------------------------------
extern "C" void kernel_launch(void* const* d_in, const int* in_sizes, int n_in,
                              void* d_out, int out_size)
{
    (void)in_sizes; (void)n_in; (void)out_size;
    const float* query    = (const float*)d_in[0];
    const float* key      = (const float*)d_in[1];
    const float* value    = (const float*)d_in[2];
    const float* rel_bias = (const float*)d_in[4];
    const float* Wq       = (const float*)d_in[5];
    const float* Wk       = (const float*)d_in[6];
    const float* Wv       = (const float*)d_in[7];
    const float* Wo       = (const float*)d_in[8];
    const float* bo       = (const float*)d_in[9];
    const int* is_causal  = (const int*)d_in[10];
    float* out            = (float*)d_out;

    const int gemm_smem = NST * STAGEB;   // 98304 B
    cudaFuncSetAttribute(gemm_qkv_kernel, cudaFuncAttributeMaxDynamicSharedMemorySize, gemm_smem);
    cudaFuncSetAttribute(gemm_out_kernel, cudaFuncAttributeMaxDynamicSharedMemorySize, gemm_smem);

    // 0) Pre-convert all GEMM operands to fp16
    f2h_kernel<<<dim3(2048, 7), 256>>>(query, key, value, Wq, Wk, Wv, Wo);

    // 1) QKV projections (fp16 mma, cp.async pipeline, z-fused)
    gemm_qkv_kernel<<<dim3(MM / 128, DD / 128, 3), 256, gemm_smem>>>();

    // 2) Bias transpose -> fp16
    bias_transpose_kernel<<<dim3(TT / 256, TT, BB), 256>>>(rel_bias);

    // 3) Flash attention (fp16 mma + ldmatrix, cp.async double-buffered K/V/bias)
    const int attn_smem = (4 * KVSZ + 3 * BSSZ) * (int)sizeof(__half); // 120832 B
    cudaFuncSetAttribute(attn_h_kernel, cudaFuncAttributeMaxDynamicSharedMemorySize, attn_smem);
    attn_h_kernel<<<dim3(TT / 128, HH, BB), 256, attn_smem>>>(is_causal);

    // 4) Output projection + bias (fp16 mma, cp.async pipeline)
    gemm_out_kernel<<<dim3(MM / 128, DD / 128), 256, gemm_smem>>>(bo, out);
}

// round 11
// speedup vs baseline: 8.1902x; 1.0122x over previous
#include <cuda_runtime.h>
#include <cuda_fp16.h>
#include <cstdint>

// Problem constants
#define BB   2
#define TT   2048
#define DD   1024
#define HH   8
#define DKK  128
#define MM   (BB*TT)

// ---------------------------------------------------------------------------
// Scratch (device globals — no allocations allowed). All intermediates fp16.
// ---------------------------------------------------------------------------
__device__ __half g_Qh[(size_t)BB*HH*TT*DKK];      // [B,H,T,DK] (pre-scaled by 1/sqrt(dk))
__device__ __half g_Kh[(size_t)BB*HH*TT*DKK];
__device__ __half g_Vh[(size_t)BB*HH*TT*DKK];
__device__ __half g_AOh[(size_t)BB*TT*DD];         // [B,T,D]
__device__ __half g_biasTh[(size_t)BB*HH*TT*TT];   // [B,H,Tq,Tk] 128 MB

// fp16 copies of GEMM operands (pre-converted once)
__device__ __half g_Xqh[(size_t)MM*DD];
__device__ __half g_Xkh[(size_t)MM*DD];
__device__ __half g_Xvh[(size_t)MM*DD];
__device__ __half g_Wqh[(size_t)DD*DD];
__device__ __half g_Wkh[(size_t)DD*DD];
__device__ __half g_Wvh[(size_t)DD*DD];
__device__ __half g_Woh[(size_t)DD*DD];

// ---------------------------------------------------------------------------
// Helpers
// ---------------------------------------------------------------------------
__device__ __forceinline__ __half2 h2(float x, float y) { return __floats2half2_rn(x, y); }
__device__ __forceinline__ unsigned packh2(float x, float y) {
    __half2 v = __floats2half2_rn(x, y);
    return *(unsigned*)&v;
}
__device__ __forceinline__ uint4 pack8(float4 a, float4 b) {
    uint4 u;
    u.x = packh2(a.x, a.y); u.y = packh2(a.z, a.w);
    u.z = packh2(b.x, b.y); u.w = packh2(b.z, b.w);
    return u;
}
__device__ __forceinline__ void ldsm4(unsigned r[4], const __half* p) {
    unsigned a = (unsigned)__cvta_generic_to_shared((void*)p);
    asm volatile("ldmatrix.sync.aligned.m8n8.x4.shared.b16 {%0,%1,%2,%3}, [%4];"
                 : "=r"(r[0]), "=r"(r[1]), "=r"(r[2]), "=r"(r[3]) : "r"(a));
}
__device__ __forceinline__ void ldsm4t(unsigned r[4], const __half* p) {
    unsigned a = (unsigned)__cvta_generic_to_shared((void*)p);
    asm volatile("ldmatrix.sync.aligned.m8n8.x4.trans.shared.b16 {%0,%1,%2,%3}, [%4];"
                 : "=r"(r[0]), "=r"(r[1]), "=r"(r[2]), "=r"(r[3]) : "r"(a));
}
__device__ __forceinline__ void mma16(float c[4], const unsigned a[4],
                                      unsigned b0, unsigned b1) {
    asm volatile(
        "mma.sync.aligned.m16n8k16.row.col.f32.f16.f16.f32 "
        "{%0,%1,%2,%3},{%4,%5,%6,%7},{%8,%9},{%0,%1,%2,%3};"
        : "+f"(c[0]), "+f"(c[1]), "+f"(c[2]), "+f"(c[3])
        : "r"(a[0]), "r"(a[1]), "r"(a[2]), "r"(a[3]), "r"(b0), "r"(b1));
}
__device__ __forceinline__ void cpa16(const __half* smem_dst, const __half* gsrc) {
    unsigned d = (unsigned)__cvta_generic_to_shared((void*)smem_dst);
    asm volatile("cp.async.cg.shared.global [%0], [%1], 16;" :: "r"(d), "l"(gsrc));
}
__device__ __forceinline__ void cpa_commit() {
    asm volatile("cp.async.commit_group;" ::: "memory");
}
template<int N> __device__ __forceinline__ void cpa_wait() {
    asm volatile("cp.async.wait_group %0;" :: "n"(N) : "memory");
}

// SW128-style swizzle over 128-byte rows (byte offset within a tile)
#define SWZ(off) ((off) ^ (((off) >> 3) & 0x70))

// ---------------------------------------------------------------------------
// Pre-convert fp32 -> fp16 (7 arrays, blockIdx.y selects)
// ---------------------------------------------------------------------------
__global__ void __launch_bounds__(256) f2h_kernel(
    const float* __restrict__ q, const float* __restrict__ k, const float* __restrict__ v,
    const float* __restrict__ wq, const float* __restrict__ wk,
    const float* __restrict__ wv, const float* __restrict__ wo)
{
    const int y = blockIdx.y;
    const float* src; __half* dst; size_t n;
    switch (y) {
        case 0: src = q;  dst = g_Xqh; n = (size_t)MM * DD; break;
        case 1: src = k;  dst = g_Xkh; n = (size_t)MM * DD; break;
        case 2: src = v;  dst = g_Xvh; n = (size_t)MM * DD; break;
        case 3: src = wq; dst = g_Wqh; n = (size_t)DD * DD; break;
        case 4: src = wk; dst = g_Wkh; n = (size_t)DD * DD; break;
        case 5: src = wv; dst = g_Wvh; n = (size_t)DD * DD; break;
        default: src = wo; dst = g_Woh; n = (size_t)DD * DD; break;
    }
    size_t i = ((size_t)blockIdx.x * 256 + threadIdx.x) * 8;
    if (i >= n) return;
    float4 a = *(const float4*)(src + i);
    float4 b = *(const float4*)(src + i + 4);
    *(uint4*)(dst + i) = pack8(a, b);
}

// ---------------------------------------------------------------------------
// fp16 GEMM, cp.async 3-stage pipeline (unchanged)
// ---------------------------------------------------------------------------
#define NST    3
#define TILEB  16384
#define STAGEB (2 * TILEB)
#define NKT    (DD / 64)

__device__ __forceinline__ void gemm_issue_stage(
    char* sm, int buf, const __half* X, const __half* W, int kt, int tid)
{
    char* A = sm + buf * STAGEB;
    char* B = A + TILEB;
#pragma unroll
    for (int j = 0; j < 4; j++) {
        int u = tid + j * 256;
        int row = u >> 3, ch = u & 7;
        int off = SWZ(row * 128 + ch * 16);
        const __half* xs = X + (size_t)row * DD + kt * 64 + ch * 8;
        const __half* ws = W + (size_t)row * DD + kt * 64 + ch * 8;
        cpa16((__half*)(A + off), xs);
        cpa16((__half*)(B + off), ws);
    }
    cpa_commit();
}

__device__ __forceinline__ void gemm_pipeline(
    const __half* Xb, const __half* Wb, int m0, int n0,
    char* sm, float acc[4][4][4])
{
    const int tid = threadIdx.x;
    const int lane = tid & 31, wid = tid >> 5;
    const int wm = (wid & 1) * 64, wn = (wid >> 1) * 32;

#pragma unroll
    for (int mf = 0; mf < 4; mf++)
#pragma unroll
        for (int nf = 0; nf < 4; nf++)
#pragma unroll
            for (int r = 0; r < 4; r++) acc[mf][nf][r] = 0.0f;

    const __half* X = Xb + (size_t)m0 * DD;
    const __half* W = Wb + (size_t)n0 * DD;

    gemm_issue_stage(sm, 0, X, W, 0, tid);
    gemm_issue_stage(sm, 1, X, W, 1, tid);

    const int rA = wm + ((lane >> 3) & 1) * 8 + (lane & 7);
    const int rB = wn + (lane >> 4) * 8 + (lane & 7);
    const int cAbase = (lane >> 4);
    const int cBbase = ((lane >> 3) & 1);

    for (int kt = 0; kt < NKT; kt++) {
        cpa_wait<NST - 2>();
        __syncthreads();
        if (kt + NST - 1 < NKT)
            gemm_issue_stage(sm, (kt + NST - 1) % NST, X, W, kt + NST - 1, tid);

        char* A = sm + (kt % NST) * STAGEB;
        char* B = A + TILEB;

#pragma unroll
        for (int ks = 0; ks < 4; ks++) {
            unsigned af[4][4];
#pragma unroll
            for (int mf = 0; mf < 4; mf++) {
                int off = SWZ((rA + mf * 16) * 128 + (2 * ks + cAbase) * 16);
                ldsm4(af[mf], (const __half*)(A + off));
            }
#pragma unroll
            for (int nfp = 0; nfp < 2; nfp++) {
                unsigned bf[4];
                int off = SWZ((rB + nfp * 16) * 128 + (2 * ks + cBbase) * 16);
                ldsm4(bf, (const __half*)(B + off));
#pragma unroll
                for (int mf = 0; mf < 4; mf++) {
                    mma16(acc[mf][nfp * 2],     af[mf], bf[0], bf[1]);
                    mma16(acc[mf][nfp * 2 + 1], af[mf], bf[2], bf[3]);
                }
            }
        }
        __syncthreads();
    }
}

__global__ void __launch_bounds__(256) gemm_qkv_kernel()
{
    extern __shared__ char sm[];
    const int z = blockIdx.z;
    const __half* X = (z == 0) ? g_Xqh : (z == 1) ? g_Xkh : g_Xvh;
    const __half* W = (z == 0) ? g_Wqh : (z == 1) ? g_Wkh : g_Wvh;
    __half* outp   = (z == 0) ? g_Qh  : (z == 1) ? g_Kh  : g_Vh;
    const float sc = (z == 0) ? 0.08838834764831845f : 1.0f;

    const int m0 = blockIdx.x * 128, n0 = blockIdx.y * 128;
    float acc[4][4][4];
    gemm_pipeline(X, W, m0, n0, sm, acc);

    const int lane = threadIdx.x & 31, wid = threadIdx.x >> 5;
    const int wm = (wid & 1) * 64, wn = (wid >> 1) * 32;
    const int g = lane >> 2, c = lane & 3;

#pragma unroll
    for (int mf = 0; mf < 4; mf++) {
        int row = m0 + wm + mf * 16 + g;
#pragma unroll
        for (int nf = 0; nf < 4; nf++) {
            int col = n0 + wn + nf * 8 + 2 * c;
            int h = col >> 7, dk = col & 127;
            {
                int b = row >> 11, t = row & 2047;
                *(__half2*)(outp + ((size_t)(b * HH + h) * TT + t) * DKK + dk) =
                    h2(acc[mf][nf][0] * sc, acc[mf][nf][1] * sc);
            }
            {
                int row2 = row + 8;
                int b = row2 >> 11, t = row2 & 2047;
                *(__half2*)(outp + ((size_t)(b * HH + h) * TT + t) * DKK + dk) =
                    h2(acc[mf][nf][2] * sc, acc[mf][nf][3] * sc);
            }
        }
    }
}

__global__ void __launch_bounds__(256) gemm_out_kernel(
    const float* __restrict__ bo, float* __restrict__ out)
{
    extern __shared__ char sm[];
    const int m0 = blockIdx.x * 128, n0 = blockIdx.y * 128;
    float acc[4][4][4];
    gemm_pipeline(g_AOh, g_Woh, m0, n0, sm, acc);

    const int lane = threadIdx.x & 31, wid = threadIdx.x >> 5;
    const int wm = (wid & 1) * 64, wn = (wid >> 1) * 32;
    const int g = lane >> 2, c = lane & 3;

#pragma unroll
    for (int mf = 0; mf < 4; mf++) {
        int row = m0 + wm + mf * 16 + g;
#pragma unroll
        for (int nf = 0; nf < 4; nf++) {
            int col = n0 + wn + nf * 8 + 2 * c;
            float2 bias = *(const float2*)(bo + col);
            *(float2*)(out + (size_t)row * DD + col) =
                make_float2(acc[mf][nf][0] + bias.x, acc[mf][nf][1] + bias.y);
            *(float2*)(out + (size_t)(row + 8) * DD + col) =
                make_float2(acc[mf][nf][2] + bias.x, acc[mf][nf][3] + bias.y);
        }
    }
}

// ---------------------------------------------------------------------------
// rel_bias transpose [B,Tq,Tk,H] fp32 -> [B,H,Tq,Tk] fp16  (unchanged)
// ---------------------------------------------------------------------------
__global__ void __launch_bounds__(256) bias_transpose_kernel(const float* __restrict__ rb)
{
    __shared__ __half smt[8][264];
    const int b = blockIdx.z, q = blockIdx.y, kc = blockIdx.x * 256;
    const int k = threadIdx.x;

    const float* src = rb + ((size_t)(b * TT + q) * TT + kc + k) * HH;
    float4 v0 = *(const float4*)(src);
    float4 v1 = *(const float4*)(src + 4);
    smt[0][k] = __float2half(v0.x); smt[1][k] = __float2half(v0.y);
    smt[2][k] = __float2half(v0.z); smt[3][k] = __float2half(v0.w);
    smt[4][k] = __float2half(v1.x); smt[5][k] = __float2half(v1.y);
    smt[6][k] = __float2half(v1.z); smt[7][k] = __float2half(v1.w);
    __syncthreads();
#pragma unroll
    for (int h = 0; h < HH; h++)
        g_biasTh[((size_t)(b * HH + h) * TT + q) * TT + kc + k] = smt[h][k];
}

// ---------------------------------------------------------------------------
// Flash attention: 4 warps / 64 q rows / 2 CTAs per SM.
// cp.async double-buffered K/V/bias; P reuses the consumed bias buffer.
// smem: K[2] 16KB, V[2] 16KB, Bias[2] 9KB  => 83968 B -> 2 CTAs/SM.
// ---------------------------------------------------------------------------
#define SATT(r) (((((r) & 1) << 2) | ((r) & 2) | (((r) >> 2) & 1)))
#define AIDX(r, c) (((r) << 7) + ((((c) ^ SATT((r) & 7))) << 3))
#define APSTR 72
#define KVSZ  (64 * 128)              // halves per K or V tile
#define BSSZ  (64 * APSTR)            // halves per bias tile (64 q rows)

__device__ __forceinline__ void attn_stage(
    __half* Ks, __half* Vs, __half* Bs,
    const __half* Kg, const __half* Vg, const __half* Bgt, int tid)
{
    // K/V: 64 rows x 16 chunks; 128 threads -> 2 threads/row, 8 chunks each
    const int srow = tid >> 1, scb = tid & 1;
    const __half* kg = Kg + (size_t)srow * DKK + scb * 8;
    const __half* vg = Vg + (size_t)srow * DKK + scb * 8;
#pragma unroll
    for (int j = 0; j < 8; j++) {
        int ch = scb + 2 * j;
        cpa16(Ks + AIDX(srow, ch), kg + 16 * j);
        cpa16(Vs + AIDX(srow, ch), vg + 16 * j);
    }
    // bias: 64 rows x 8 chunks = 512 -> 4 per thread
#pragma unroll
    for (int j = 0; j < 4; j++) {
        int u = tid + 128 * j;
        int row = u >> 3, ch = u & 7;
        cpa16(Bs + row * APSTR + ch * 8, Bgt + (size_t)row * TT + ch * 8);
    }
    cpa_commit();
}

__global__ void __launch_bounds__(128, 2) attn_h_kernel(const int* __restrict__ is_causal_p)
{
    extern __shared__ __half smh[];
    __half* Kb[2] = { smh,             smh + KVSZ };
    __half* Vb[2] = { smh + 2 * KVSZ,  smh + 3 * KVSZ };
    __half* Bb[2] = { smh + 4 * KVSZ,  smh + 4 * KVSZ + BSSZ };

    const int q0 = ((int)gridDim.x - 1 - (int)blockIdx.x) * 64;  // long CTAs first
    const int h = blockIdx.y, b = blockIdx.z;
    const int tid = threadIdx.x, lane = tid & 31, w = tid >> 5;   // w in 0..3
    const int g = lane >> 2, c = lane & 3;
    const bool causal = (is_causal_p[0] != 0);

    const __half* Qg = g_Qh + (size_t)(b * HH + h) * TT * DKK;
    const __half* Kg = g_Kh + (size_t)(b * HH + h) * TT * DKK;
    const __half* Vg = g_Vh + (size_t)(b * HH + h) * TT * DKK;
    const __half* Bg = g_biasTh + (size_t)(b * HH + h) * TT * TT + (size_t)q0 * TT;

    const int r0 = q0 + w * 16 + g;

    // Q A-fragments, register-resident (Q already scaled by 1/sqrt(dk))
    unsigned qa[8][4];
#pragma unroll
    for (int ks = 0; ks < 8; ks++) {
        const __half* p = Qg + (size_t)r0 * DKK + ks * 16 + 2 * c;
        qa[ks][0] = *(const unsigned*)(p);
        qa[ks][1] = *(const unsigned*)(p + 8 * DKK);
        qa[ks][2] = *(const unsigned*)(p + 8);
        qa[ks][3] = *(const unsigned*)(p + 8 * DKK + 8);
    }

    float o[16][4];
#pragma unroll
    for (int nf = 0; nf < 16; nf++)
#pragma unroll
        for (int r = 0; r < 4; r++) o[nf][r] = 0.0f;
    float mi[2] = {-1e30f, -1e30f}, li[2] = {0.0f, 0.0f};

    const int ntiles = causal ? (q0 / 64 + 1) : (TT / 64);

    // prologue: stage tile 0
    attn_stage(Kb[0], Vb[0], Bb[0], Kg, Vg, Bg, tid);

    for (int kt = 0; kt < ntiles; kt++) {
        const int k0 = kt * 64;
        const int buf = kt & 1;

        if (kt + 1 < ntiles) {
            const int k1 = (kt + 1) * 64;
            attn_stage(Kb[buf ^ 1], Vb[buf ^ 1], Bb[buf ^ 1],
                       Kg + (size_t)k1 * DKK, Vg + (size_t)k1 * DKK, Bg + k1, tid);
            cpa_wait<1>();
        } else {
            cpa_wait<0>();
        }
        __syncthreads();

        __half* Ks = Kb[buf];
        __half* Vs = Vb[buf];
        __half* Bs = Bb[buf];      // bias now; reused as P after S-init
        __half* Ps = Bs;

        // S accum initialized with bias (from smem, conflict-free)
        float s[8][4];
#pragma unroll
        for (int nf = 0; nf < 8; nf++) {
            const __half* bp = Bs + (w * 16 + g) * APSTR + nf * 8 + 2 * c;
            float2 b01 = __half22float2(*(const __half2*)bp);
            float2 b23 = __half22float2(*(const __half2*)(bp + 8 * APSTR));
            s[nf][0] = b01.x; s[nf][1] = b01.y; s[nf][2] = b23.x; s[nf][3] = b23.y;
        }

        // S += Q K^T
#pragma unroll
        for (int ks = 0; ks < 8; ks++) {
#pragma unroll
            for (int nfp = 0; nfp < 4; nfp++) {
                unsigned bf[4];
                int rB = nfp * 16 + (lane >> 4) * 8 + (lane & 7);
                int cB = 2 * ks + ((lane >> 3) & 1);
                ldsm4(bf, Ks + AIDX(rB, cB));
                mma16(s[nfp * 2],     qa[ks], bf[0], bf[1]);
                mma16(s[nfp * 2 + 1], qa[ks], bf[2], bf[3]);
            }
        }

        // Causal mask (only diagonal-crossing tiles for this warp)
        if (causal && k0 + 63 > q0 + w * 16) {
#pragma unroll
            for (int nf = 0; nf < 8; nf++) {
                int col = k0 + nf * 8 + 2 * c;
                if (col     > r0)     s[nf][0] = -1e30f;
                if (col + 1 > r0)     s[nf][1] = -1e30f;
                if (col     > r0 + 8) s[nf][2] = -1e30f;
                if (col + 1 > r0 + 8) s[nf][3] = -1e30f;
            }
        }

        // Online softmax (row pair {r0, r0+8}); quad reduce via xor 1,2
#pragma unroll
        for (int r = 0; r < 2; r++) {
            const int i0 = 2 * r, i1 = 2 * r + 1;
            float rmax = -1e30f;
#pragma unroll
            for (int nf = 0; nf < 8; nf++)
                rmax = fmaxf(rmax, fmaxf(s[nf][i0], s[nf][i1]));
            rmax = fmaxf(rmax, __shfl_xor_sync(0xffffffffu, rmax, 1));
            rmax = fmaxf(rmax, __shfl_xor_sync(0xffffffffu, rmax, 2));
            float mnew = fmaxf(mi[r], rmax);
            float corr = __expf(mi[r] - mnew);
            float psum = 0.0f;
#pragma unroll
            for (int nf = 0; nf < 8; nf++) {
                float p0 = __expf(s[nf][i0] - mnew);
                float p1 = __expf(s[nf][i1] - mnew);
                s[nf][i0] = p0; s[nf][i1] = p1;
                psum += p0 + p1;
            }
            psum += __shfl_xor_sync(0xffffffffu, psum, 1);
            psum += __shfl_xor_sync(0xffffffffu, psum, 2);
            li[r] = li[r] * corr + psum;
            mi[r] = mnew;
#pragma unroll
            for (int nf = 0; nf < 16; nf++) { o[nf][i0] *= corr; o[nf][i1] *= corr; }
        }

        // P -> per-warp smem region (reuses bias buffer; warp-private rows)
#pragma unroll
        for (int nf = 0; nf < 8; nf++) {
            *(__half2*)(Ps + (w * 16 + g) * APSTR + nf * 8 + 2 * c)     = h2(s[nf][0], s[nf][1]);
            *(__half2*)(Ps + (w * 16 + g + 8) * APSTR + nf * 8 + 2 * c) = h2(s[nf][2], s[nf][3]);
        }
        __syncwarp();

        // O += P @ V
#pragma unroll
        for (int kst = 0; kst < 4; kst++) {
            unsigned pa[4];
            const __half* pp = Ps + (w * 16 + ((lane >> 3) & 1) * 8 + (lane & 7)) * APSTR
                                  + kst * 16 + (lane >> 4) * 8;
            ldsm4(pa, pp);
#pragma unroll
            for (int nfp = 0; nfp < 8; nfp++) {
                unsigned vb[4];
                int rV = kst * 16 + ((lane >> 3) & 1) * 8 + (lane & 7);
                int cV = nfp * 2 + (lane >> 4);
                ldsm4t(vb, Vs + AIDX(rV, cV));
                mma16(o[nfp * 2],     pa, vb[0], vb[1]);
                mma16(o[nfp * 2 + 1], pa, vb[2], vb[3]);
            }
        }
        __syncthreads();
    }

    // Epilogue: normalize, write fp16 AO in [B,T,D]
    const float inv0 = 1.0f / li[0], inv1 = 1.0f / li[1];
    __half* dst0 = g_AOh + ((size_t)(b * TT + r0) * DD) + h * DKK;
    __half* dst1 = dst0 + (size_t)8 * DD;
#pragma unroll
    for (int nf = 0; nf < 16; nf++) {
        int col = nf * 8 + 2 * c;
        *(__half2*)(dst0 + col) = h2(o[nf][0] * inv0, o[nf][1] * inv0);
        *(__half2*)(dst1 + col) = h2(o[nf][2] * inv1, o[nf][3] * inv1);
    }
}

// ---------------------------------------------------------------------------
// Launcher. Inputs: 0 query, 1 key, 2 value, 3 mask(all-false, unused),
// 4 rel_bias, 5 Wq, 6 Wk, 7 Wv, 8 Wo, 9 bo, 10 is_causal
// ---------------------------------------------------------------------------
extern "C" void kernel_launch(void* const* d_in, const int* in_sizes, int n_in,
                              void* d_out, int out_size)
{
    (void)in_sizes; (void)n_in; (void)out_size;
    const float* query    = (const float*)d_in[0];
    const float* key      = (const float*)d_in[1];
    const float* value    = (const float*)d_in[2];
    const float* rel_bias = (const float*)d_in[4];
    const float* Wq       = (const float*)d_in[5];
    const float* Wk       = (const float*)d_in[6];
    const float* Wv       = (const float*)d_in[7];
    const float* Wo       = (const float*)d_in[8];
    const float* bo       = (const float*)d_in[9];
    const int* is_causal  = (const int*)d_in[10];
    float* out            = (float*)d_out;

    const int gemm_smem = NST * STAGEB;   // 98304 B
    cudaFuncSetAttribute(gemm_qkv_kernel, cudaFuncAttributeMaxDynamicSharedMemorySize, gemm_smem);
    cudaFuncSetAttribute(gemm_out_kernel, cudaFuncAttributeMaxDynamicSharedMemorySize, gemm_smem);

    // 0) Pre-convert all GEMM operands to fp16
    f2h_kernel<<<dim3(2048, 7), 256>>>(query, key, value, Wq, Wk, Wv, Wo);

    // 1) QKV projections (fp16 mma, cp.async pipeline, z-fused)
    gemm_qkv_kernel<<<dim3(MM / 128, DD / 128, 3), 256, gemm_smem>>>();

    // 2) Bias transpose -> fp16
    bias_transpose_kernel<<<dim3(TT / 256, TT, BB), 256>>>(rel_bias);

    // 3) Flash attention: 64 q rows/CTA, 4 warps, 2 CTAs/SM
    const int attn_smem = (4 * KVSZ + 2 * BSSZ) * (int)sizeof(__half); // 83968 B
    cudaFuncSetAttribute(attn_h_kernel, cudaFuncAttributeMaxDynamicSharedMemorySize, attn_smem);
    attn_h_kernel<<<dim3(TT / 64, HH, BB), 128, attn_smem>>>(is_causal);

    // 4) Output projection + bias (fp16 mma, cp.async pipeline)
    gemm_out_kernel<<<dim3(MM / 128, DD / 128), 256, gemm_smem>>>(bo, out);
}

// round 12
// speedup vs baseline: 9.0744x; 1.1080x over previous
#include <cuda_runtime.h>
#include <cuda_fp16.h>
#include <cstdint>

// Problem constants
#define BB   2
#define TT   2048
#define DD   1024
#define HH   8
#define DKK  128
#define MM   (BB*TT)

// ---------------------------------------------------------------------------
// Scratch (device globals — no allocations allowed). All intermediates fp16.
// ---------------------------------------------------------------------------
__device__ __half g_Qh[(size_t)BB*HH*TT*DKK];      // [B,H,T,DK] (pre-scaled by 1/sqrt(dk))
__device__ __half g_Kh[(size_t)BB*HH*TT*DKK];
__device__ __half g_Vh[(size_t)BB*HH*TT*DKK];
__device__ __half g_AOh[(size_t)BB*TT*DD];         // [B,T,D]
__device__ __half g_biasTh[(size_t)BB*HH*TT*TT];   // [B,H,Tq,Tk] 128 MB

// fp16 copies of GEMM operands (pre-converted once)
__device__ __half g_Xqh[(size_t)MM*DD];
__device__ __half g_Xkh[(size_t)MM*DD];
__device__ __half g_Xvh[(size_t)MM*DD];
__device__ __half g_Wqh[(size_t)DD*DD];
__device__ __half g_Wkh[(size_t)DD*DD];
__device__ __half g_Wvh[(size_t)DD*DD];
__device__ __half g_Woh[(size_t)DD*DD];

// ---------------------------------------------------------------------------
// Helpers
// ---------------------------------------------------------------------------
__device__ __forceinline__ __half2 h2(float x, float y) { return __floats2half2_rn(x, y); }
__device__ __forceinline__ unsigned packh2(float x, float y) {
    __half2 v = __floats2half2_rn(x, y);
    return *(unsigned*)&v;
}
__device__ __forceinline__ uint4 pack8(float4 a, float4 b) {
    uint4 u;
    u.x = packh2(a.x, a.y); u.y = packh2(a.z, a.w);
    u.z = packh2(b.x, b.y); u.w = packh2(b.z, b.w);
    return u;
}
__device__ __forceinline__ void ldsm4(unsigned r[4], const __half* p) {
    unsigned a = (unsigned)__cvta_generic_to_shared((void*)p);
    asm volatile("ldmatrix.sync.aligned.m8n8.x4.shared.b16 {%0,%1,%2,%3}, [%4];"
                 : "=r"(r[0]), "=r"(r[1]), "=r"(r[2]), "=r"(r[3]) : "r"(a));
}
__device__ __forceinline__ void ldsm4t(unsigned r[4], const __half* p) {
    unsigned a = (unsigned)__cvta_generic_to_shared((void*)p);
    asm volatile("ldmatrix.sync.aligned.m8n8.x4.trans.shared.b16 {%0,%1,%2,%3}, [%4];"
                 : "=r"(r[0]), "=r"(r[1]), "=r"(r[2]), "=r"(r[3]) : "r"(a));
}
__device__ __forceinline__ void mma16(float c[4], const unsigned a[4],
                                      unsigned b0, unsigned b1) {
    asm volatile(
        "mma.sync.aligned.m16n8k16.row.col.f32.f16.f16.f32 "
        "{%0,%1,%2,%3},{%4,%5,%6,%7},{%8,%9},{%0,%1,%2,%3};"
        : "+f"(c[0]), "+f"(c[1]), "+f"(c[2]), "+f"(c[3])
        : "r"(a[0]), "r"(a[1]), "r"(a[2]), "r"(a[3]), "r"(b0), "r"(b1));
}
__device__ __forceinline__ void cpa16(const __half* smem_dst, const __half* gsrc) {
    unsigned d = (unsigned)__cvta_generic_to_shared((void*)smem_dst);
    asm volatile("cp.async.cg.shared.global [%0], [%1], 16;" :: "r"(d), "l"(gsrc));
}
__device__ __forceinline__ void cpa_commit() {
    asm volatile("cp.async.commit_group;" ::: "memory");
}
template<int N> __device__ __forceinline__ void cpa_wait() {
    asm volatile("cp.async.wait_group %0;" :: "n"(N) : "memory");
}

// SW128-style swizzle over 128-byte rows (byte offset within a tile)
#define SWZ(off) ((off) ^ (((off) >> 3) & 0x70))

// ---------------------------------------------------------------------------
// Pre-convert fp32 -> fp16 (7 arrays, blockIdx.y selects)
// ---------------------------------------------------------------------------
__global__ void __launch_bounds__(256) f2h_kernel(
    const float* __restrict__ q, const float* __restrict__ k, const float* __restrict__ v,
    const float* __restrict__ wq, const float* __restrict__ wk,
    const float* __restrict__ wv, const float* __restrict__ wo)
{
    const int y = blockIdx.y;
    const float* src; __half* dst; size_t n;
    switch (y) {
        case 0: src = q;  dst = g_Xqh; n = (size_t)MM * DD; break;
        case 1: src = k;  dst = g_Xkh; n = (size_t)MM * DD; break;
        case 2: src = v;  dst = g_Xvh; n = (size_t)MM * DD; break;
        case 3: src = wq; dst = g_Wqh; n = (size_t)DD * DD; break;
        case 4: src = wk; dst = g_Wkh; n = (size_t)DD * DD; break;
        case 5: src = wv; dst = g_Wvh; n = (size_t)DD * DD; break;
        default: src = wo; dst = g_Woh; n = (size_t)DD * DD; break;
    }
    size_t i = ((size_t)blockIdx.x * 256 + threadIdx.x) * 8;
    if (i >= n) return;
    float4 a = *(const float4*)(src + i);
    float4 b = *(const float4*)(src + i + 4);
    *(uint4*)(dst + i) = pack8(a, b);
}

// ---------------------------------------------------------------------------
// fp16 GEMM, cp.async 3-stage pipeline (unchanged)
// ---------------------------------------------------------------------------
#define NST    3
#define TILEB  16384
#define STAGEB (2 * TILEB)
#define NKT    (DD / 64)

__device__ __forceinline__ void gemm_issue_stage(
    char* sm, int buf, const __half* X, const __half* W, int kt, int tid)
{
    char* A = sm + buf * STAGEB;
    char* B = A + TILEB;
#pragma unroll
    for (int j = 0; j < 4; j++) {
        int u = tid + j * 256;
        int row = u >> 3, ch = u & 7;
        int off = SWZ(row * 128 + ch * 16);
        const __half* xs = X + (size_t)row * DD + kt * 64 + ch * 8;
        const __half* ws = W + (size_t)row * DD + kt * 64 + ch * 8;
        cpa16((__half*)(A + off), xs);
        cpa16((__half*)(B + off), ws);
    }
    cpa_commit();
}

__device__ __forceinline__ void gemm_pipeline(
    const __half* Xb, const __half* Wb, int m0, int n0,
    char* sm, float acc[4][4][4])
{
    const int tid = threadIdx.x;
    const int lane = tid & 31, wid = tid >> 5;
    const int wm = (wid & 1) * 64, wn = (wid >> 1) * 32;

#pragma unroll
    for (int mf = 0; mf < 4; mf++)
#pragma unroll
        for (int nf = 0; nf < 4; nf++)
#pragma unroll
            for (int r = 0; r < 4; r++) acc[mf][nf][r] = 0.0f;

    const __half* X = Xb + (size_t)m0 * DD;
    const __half* W = Wb + (size_t)n0 * DD;

    gemm_issue_stage(sm, 0, X, W, 0, tid);
    gemm_issue_stage(sm, 1, X, W, 1, tid);

    const int rA = wm + ((lane >> 3) & 1) * 8 + (lane & 7);
    const int rB = wn + (lane >> 4) * 8 + (lane & 7);
    const int cAbase = (lane >> 4);
    const int cBbase = ((lane >> 3) & 1);

    for (int kt = 0; kt < NKT; kt++) {
        cpa_wait<NST - 2>();
        __syncthreads();
        if (kt + NST - 1 < NKT)
            gemm_issue_stage(sm, (kt + NST - 1) % NST, X, W, kt + NST - 1, tid);

        char* A = sm + (kt % NST) * STAGEB;
        char* B = A + TILEB;

#pragma unroll
        for (int ks = 0; ks < 4; ks++) {
            unsigned af[4][4];
#pragma unroll
            for (int mf = 0; mf < 4; mf++) {
                int off = SWZ((rA + mf * 16) * 128 + (2 * ks + cAbase) * 16);
                ldsm4(af[mf], (const __half*)(A + off));
            }
#pragma unroll
            for (int nfp = 0; nfp < 2; nfp++) {
                unsigned bf[4];
                int off = SWZ((rB + nfp * 16) * 128 + (2 * ks + cBbase) * 16);
                ldsm4(bf, (const __half*)(B + off));
#pragma unroll
                for (int mf = 0; mf < 4; mf++) {
                    mma16(acc[mf][nfp * 2],     af[mf], bf[0], bf[1]);
                    mma16(acc[mf][nfp * 2 + 1], af[mf], bf[2], bf[3]);
                }
            }
        }
        __syncthreads();
    }
}

__global__ void __launch_bounds__(256) gemm_qkv_kernel()
{
    extern __shared__ char sm[];
    const int z = blockIdx.z;
    const __half* X = (z == 0) ? g_Xqh : (z == 1) ? g_Xkh : g_Xvh;
    const __half* W = (z == 0) ? g_Wqh : (z == 1) ? g_Wkh : g_Wvh;
    __half* outp   = (z == 0) ? g_Qh  : (z == 1) ? g_Kh  : g_Vh;
    const float sc = (z == 0) ? 0.08838834764831845f : 1.0f;

    const int m0 = blockIdx.x * 128, n0 = blockIdx.y * 128;
    float acc[4][4][4];
    gemm_pipeline(X, W, m0, n0, sm, acc);

    const int lane = threadIdx.x & 31, wid = threadIdx.x >> 5;
    const int wm = (wid & 1) * 64, wn = (wid >> 1) * 32;
    const int g = lane >> 2, c = lane & 3;

#pragma unroll
    for (int mf = 0; mf < 4; mf++) {
        int row = m0 + wm + mf * 16 + g;
#pragma unroll
        for (int nf = 0; nf < 4; nf++) {
            int col = n0 + wn + nf * 8 + 2 * c;
            int h = col >> 7, dk = col & 127;
            {
                int b = row >> 11, t = row & 2047;
                *(__half2*)(outp + ((size_t)(b * HH + h) * TT + t) * DKK + dk) =
                    h2(acc[mf][nf][0] * sc, acc[mf][nf][1] * sc);
            }
            {
                int row2 = row + 8;
                int b = row2 >> 11, t = row2 & 2047;
                *(__half2*)(outp + ((size_t)(b * HH + h) * TT + t) * DKK + dk) =
                    h2(acc[mf][nf][2] * sc, acc[mf][nf][3] * sc);
            }
        }
    }
}

__global__ void __launch_bounds__(256) gemm_out_kernel(
    const float* __restrict__ bo, float* __restrict__ out)
{
    extern __shared__ char sm[];
    const int m0 = blockIdx.x * 128, n0 = blockIdx.y * 128;
    float acc[4][4][4];
    gemm_pipeline(g_AOh, g_Woh, m0, n0, sm, acc);

    const int lane = threadIdx.x & 31, wid = threadIdx.x >> 5;
    const int wm = (wid & 1) * 64, wn = (wid >> 1) * 32;
    const int g = lane >> 2, c = lane & 3;

#pragma unroll
    for (int mf = 0; mf < 4; mf++) {
        int row = m0 + wm + mf * 16 + g;
#pragma unroll
        for (int nf = 0; nf < 4; nf++) {
            int col = n0 + wn + nf * 8 + 2 * c;
            float2 bias = *(const float2*)(bo + col);
            *(float2*)(out + (size_t)row * DD + col) =
                make_float2(acc[mf][nf][0] + bias.x, acc[mf][nf][1] + bias.y);
            *(float2*)(out + (size_t)(row + 8) * DD + col) =
                make_float2(acc[mf][nf][2] + bias.x, acc[mf][nf][3] + bias.y);
        }
    }
}

// ---------------------------------------------------------------------------
// rel_bias transpose [B,Tq,Tk,H] fp32 -> [B,H,Tq,Tk] fp16.
// Causal skip: columns kc > (q|63) are never read by attention (masked),
// so skip those chunks entirely when is_causal.
// ---------------------------------------------------------------------------
__global__ void __launch_bounds__(256) bias_transpose_kernel(
    const float* __restrict__ rb, const int* __restrict__ is_causal_p)
{
    const int b = blockIdx.z, q = blockIdx.y, kc = blockIdx.x * 256;
    if (is_causal_p[0] && kc > (q | 63)) return;

    __shared__ __half smt[8][264];
    const int k = threadIdx.x;

    const float* src = rb + ((size_t)(b * TT + q) * TT + kc + k) * HH;
    float4 v0 = *(const float4*)(src);
    float4 v1 = *(const float4*)(src + 4);
    smt[0][k] = __float2half(v0.x); smt[1][k] = __float2half(v0.y);
    smt[2][k] = __float2half(v0.z); smt[3][k] = __float2half(v0.w);
    smt[4][k] = __float2half(v1.x); smt[5][k] = __float2half(v1.y);
    smt[6][k] = __float2half(v1.z); smt[7][k] = __float2half(v1.w);
    __syncthreads();
#pragma unroll
    for (int h = 0; h < HH; h++)
        g_biasTh[((size_t)(b * HH + h) * TT + q) * TT + kc + k] = smt[h][k];
}

// ---------------------------------------------------------------------------
// Flash attention: 4 warps / 64 q rows / 2 CTAs per SM.
// cp.async double-buffered K/V/bias. P stays in REGISTERS:
// the S C-fragment maps 1:1 onto the PV A-fragment (no smem round-trip).
// smem: K[2] 32KB, V[2] 32KB, Bias[2] 18KB  => 83968 B -> 2 CTAs/SM.
// ---------------------------------------------------------------------------
#define SATT(r) (((((r) & 1) << 2) | ((r) & 2) | (((r) >> 2) & 1)))
#define AIDX(r, c) (((r) << 7) + ((((c) ^ SATT((r) & 7))) << 3))
#define APSTR 72
#define KVSZ  (64 * 128)              // halves per K or V tile
#define BSSZ  (64 * APSTR)            // halves per bias tile (64 q rows)

__device__ __forceinline__ void attn_stage(
    __half* Ks, __half* Vs, __half* Bs,
    const __half* Kg, const __half* Vg, const __half* Bgt, int tid)
{
    // K/V: 64 rows x 16 chunks; 128 threads -> 2 threads/row, 8 chunks each
    const int srow = tid >> 1, scb = tid & 1;
    const __half* kg = Kg + (size_t)srow * DKK + scb * 8;
    const __half* vg = Vg + (size_t)srow * DKK + scb * 8;
#pragma unroll
    for (int j = 0; j < 8; j++) {
        int ch = scb + 2 * j;
        cpa16(Ks + AIDX(srow, ch), kg + 16 * j);
        cpa16(Vs + AIDX(srow, ch), vg + 16 * j);
    }
    // bias: 64 rows x 8 chunks = 512 -> 4 per thread
#pragma unroll
    for (int j = 0; j < 4; j++) {
        int u = tid + 128 * j;
        int row = u >> 3, ch = u & 7;
        cpa16(Bs + row * APSTR + ch * 8, Bgt + (size_t)row * TT + ch * 8);
    }
    cpa_commit();
}

__global__ void __launch_bounds__(128, 2) attn_h_kernel(const int* __restrict__ is_causal_p)
{
    extern __shared__ __half smh[];
    __half* Kb[2] = { smh,             smh + KVSZ };
    __half* Vb[2] = { smh + 2 * KVSZ,  smh + 3 * KVSZ };
    __half* Bb[2] = { smh + 4 * KVSZ,  smh + 4 * KVSZ + BSSZ };

    const int q0 = ((int)gridDim.x - 1 - (int)blockIdx.x) * 64;  // long CTAs first
    const int h = blockIdx.y, b = blockIdx.z;
    const int tid = threadIdx.x, lane = tid & 31, w = tid >> 5;   // w in 0..3
    const int g = lane >> 2, c = lane & 3;
    const bool causal = (is_causal_p[0] != 0);

    const __half* Qg = g_Qh + (size_t)(b * HH + h) * TT * DKK;
    const __half* Kg = g_Kh + (size_t)(b * HH + h) * TT * DKK;
    const __half* Vg = g_Vh + (size_t)(b * HH + h) * TT * DKK;
    const __half* Bg = g_biasTh + (size_t)(b * HH + h) * TT * TT + (size_t)q0 * TT;

    const int r0 = q0 + w * 16 + g;

    // Q A-fragments, register-resident (Q already scaled by 1/sqrt(dk))
    unsigned qa[8][4];
#pragma unroll
    for (int ks = 0; ks < 8; ks++) {
        const __half* p = Qg + (size_t)r0 * DKK + ks * 16 + 2 * c;
        qa[ks][0] = *(const unsigned*)(p);
        qa[ks][1] = *(const unsigned*)(p + 8 * DKK);
        qa[ks][2] = *(const unsigned*)(p + 8);
        qa[ks][3] = *(const unsigned*)(p + 8 * DKK + 8);
    }

    float o[16][4];
#pragma unroll
    for (int nf = 0; nf < 16; nf++)
#pragma unroll
        for (int r = 0; r < 4; r++) o[nf][r] = 0.0f;
    float mi[2] = {-1e30f, -1e30f}, li[2] = {0.0f, 0.0f};

    const int ntiles = causal ? (q0 / 64 + 1) : (TT / 64);

    // prologue: stage tile 0
    attn_stage(Kb[0], Vb[0], Bb[0], Kg, Vg, Bg, tid);

    for (int kt = 0; kt < ntiles; kt++) {
        const int k0 = kt * 64;
        const int buf = kt & 1;

        if (kt + 1 < ntiles) {
            const int k1 = (kt + 1) * 64;
            attn_stage(Kb[buf ^ 1], Vb[buf ^ 1], Bb[buf ^ 1],
                       Kg + (size_t)k1 * DKK, Vg + (size_t)k1 * DKK, Bg + k1, tid);
            cpa_wait<1>();
        } else {
            cpa_wait<0>();
        }
        __syncthreads();

        __half* Ks = Kb[buf];
        __half* Vs = Vb[buf];
        const __half* Bs = Bb[buf];

        // S accum initialized with bias (from smem, conflict-free)
        float s[8][4];
#pragma unroll
        for (int nf = 0; nf < 8; nf++) {
            const __half* bp = Bs + (w * 16 + g) * APSTR + nf * 8 + 2 * c;
            float2 b01 = __half22float2(*(const __half2*)bp);
            float2 b23 = __half22float2(*(const __half2*)(bp + 8 * APSTR));
            s[nf][0] = b01.x; s[nf][1] = b01.y; s[nf][2] = b23.x; s[nf][3] = b23.y;
        }

        // S += Q K^T
#pragma unroll
        for (int ks = 0; ks < 8; ks++) {
#pragma unroll
            for (int nfp = 0; nfp < 4; nfp++) {
                unsigned bf[4];
                int rB = nfp * 16 + (lane >> 4) * 8 + (lane & 7);
                int cB = 2 * ks + ((lane >> 3) & 1);
                ldsm4(bf, Ks + AIDX(rB, cB));
                mma16(s[nfp * 2],     qa[ks], bf[0], bf[1]);
                mma16(s[nfp * 2 + 1], qa[ks], bf[2], bf[3]);
            }
        }

        // Causal mask (only diagonal-crossing tiles for this warp)
        if (causal && k0 + 63 > q0 + w * 16) {
#pragma unroll
            for (int nf = 0; nf < 8; nf++) {
                int col = k0 + nf * 8 + 2 * c;
                if (col     > r0)     s[nf][0] = -1e30f;
                if (col + 1 > r0)     s[nf][1] = -1e30f;
                if (col     > r0 + 8) s[nf][2] = -1e30f;
                if (col + 1 > r0 + 8) s[nf][3] = -1e30f;
            }
        }

        // Online softmax (row pair {r0, r0+8}); quad reduce via xor 1,2
#pragma unroll
        for (int r = 0; r < 2; r++) {
            const int i0 = 2 * r, i1 = 2 * r + 1;
            float rmax = -1e30f;
#pragma unroll
            for (int nf = 0; nf < 8; nf++)
                rmax = fmaxf(rmax, fmaxf(s[nf][i0], s[nf][i1]));
            rmax = fmaxf(rmax, __shfl_xor_sync(0xffffffffu, rmax, 1));
            rmax = fmaxf(rmax, __shfl_xor_sync(0xffffffffu, rmax, 2));
            float mnew = fmaxf(mi[r], rmax);
            float corr = __expf(mi[r] - mnew);
            float psum = 0.0f;
#pragma unroll
            for (int nf = 0; nf < 8; nf++) {
                float p0 = __expf(s[nf][i0] - mnew);
                float p1 = __expf(s[nf][i1] - mnew);
                s[nf][i0] = p0; s[nf][i1] = p1;
                psum += p0 + p1;
            }
            psum += __shfl_xor_sync(0xffffffffu, psum, 1);
            psum += __shfl_xor_sync(0xffffffffu, psum, 2);
            li[r] = li[r] * corr + psum;
            mi[r] = mnew;
#pragma unroll
            for (int nf = 0; nf < 16; nf++) { o[nf][i0] *= corr; o[nf][i1] *= corr; }
        }

        // O += P @ V — P A-fragments built DIRECTLY from the S C-fragments
        // (thread g,c holds S rows {r0,r0+8} cols {nf*8+2c, +2c+1}; an A-frag
        //  k-chunk of 16 = nf pair {2j, 2j+1}). No smem round-trip.
#pragma unroll
        for (int kst = 0; kst < 4; kst++) {
            unsigned pa[4];
            pa[0] = packh2(s[2 * kst][0],     s[2 * kst][1]);      // row g,   k 0-7
            pa[1] = packh2(s[2 * kst][2],     s[2 * kst][3]);      // row g+8, k 0-7
            pa[2] = packh2(s[2 * kst + 1][0], s[2 * kst + 1][1]);  // row g,   k 8-15
            pa[3] = packh2(s[2 * kst + 1][2], s[2 * kst + 1][3]);  // row g+8, k 8-15
#pragma unroll
            for (int nfp = 0; nfp < 8; nfp++) {
                unsigned vb[4];
                int rV = kst * 16 + ((lane >> 3) & 1) * 8 + (lane & 7);
                int cV = nfp * 2 + (lane >> 4);
                ldsm4t(vb, Vs + AIDX(rV, cV));
                mma16(o[nfp * 2],     pa, vb[0], vb[1]);
                mma16(o[nfp * 2 + 1], pa, vb[2], vb[3]);
            }
        }
        __syncthreads();
    }

    // Epilogue: normalize, write fp16 AO in [B,T,D]
    const float inv0 = 1.0f / li[0], inv1 = 1.0f / li[1];
    __half* dst0 = g_AOh + ((size_t)(b * TT + r0) * DD) + h * DKK;
    __half* dst1 = dst0 + (size_t)8 * DD;
#pragma unroll
    for (int nf = 0; nf < 16; nf++) {
        int col = nf * 8 + 2 * c;
        *(__half2*)(dst0 + col) = h2(o[nf][0] * inv0, o[nf][1] * inv0);
        *(__half2*)(dst1 + col) = h2(o[nf][2] * inv1, o[nf][3] * inv1);
    }
}

// ---------------------------------------------------------------------------
// Launcher. Inputs: 0 query, 1 key, 2 value, 3 mask(all-false, unused),
// 4 rel_bias, 5 Wq, 6 Wk, 7 Wv, 8 Wo, 9 bo, 10 is_causal
// ---------------------------------------------------------------------------
extern "C" void kernel_launch(void* const* d_in, const int* in_sizes, int n_in,
                              void* d_out, int out_size)
{
    (void)in_sizes; (void)n_in; (void)out_size;
    const float* query    = (const float*)d_in[0];
    const float* key      = (const float*)d_in[1];
    const float* value    = (const float*)d_in[2];
    const float* rel_bias = (const float*)d_in[4];
    const float* Wq       = (const float*)d_in[5];
    const float* Wk       = (const float*)d_in[6];
    const float* Wv       = (const float*)d_in[7];
    const float* Wo       = (const float*)d_in[8];
    const float* bo       = (const float*)d_in[9];
    const int* is_causal  = (const int*)d_in[10];
    float* out            = (float*)d_out;

    const int gemm_smem = NST * STAGEB;   // 98304 B
    cudaFuncSetAttribute(gemm_qkv_kernel, cudaFuncAttributeMaxDynamicSharedMemorySize, gemm_smem);
    cudaFuncSetAttribute(gemm_out_kernel, cudaFuncAttributeMaxDynamicSharedMemorySize, gemm_smem);

    // 0) Pre-convert all GEMM operands to fp16
    f2h_kernel<<<dim3(2048, 7), 256>>>(query, key, value, Wq, Wk, Wv, Wo);

    // 1) QKV projections (fp16 mma, cp.async pipeline, z-fused)
    gemm_qkv_kernel<<<dim3(MM / 128, DD / 128, 3), 256, gemm_smem>>>();

    // 2) Bias transpose -> fp16 (causal chunks only)
    bias_transpose_kernel<<<dim3(TT / 256, TT, BB), 256>>>(rel_bias, is_causal);

    // 3) Flash attention: 64 q rows/CTA, 4 warps, 2 CTAs/SM, P in registers
    const int attn_smem = (4 * KVSZ + 2 * BSSZ) * (int)sizeof(__half); // 83968 B
    cudaFuncSetAttribute(attn_h_kernel, cudaFuncAttributeMaxDynamicSharedMemorySize, attn_smem);
    attn_h_kernel<<<dim3(TT / 64, HH, BB), 128, attn_smem>>>(is_causal);

    // 4) Output projection + bias (fp16 mma, cp.async pipeline)
    gemm_out_kernel<<<dim3(MM / 128, DD / 128), 256, gemm_smem>>>(bo, out);
}